// round 3
// baseline (speedup 1.0000x reference)
#include <cuda_runtime.h>
#include <math.h>

// ---------------------------------------------------------------------------
// Problem constants (fixed shapes from setup_inputs)
// ---------------------------------------------------------------------------
#define HWn   65536           // H*W = 256*256
#define Wimg  256
#define Himg  256
#define DIM   64
#define CH6   384             // 6*dim == 2*hidden (hidden=192)
#define CH2   128             // 2*dim (q/k/v channel count)
#define HID   192
#define NCHUNK 1024           // chunks of 64 px per channel plane
#define EPS   1e-5f

typedef unsigned long long u64;

// ---------------------------------------------------------------------------
// Scratch (static device globals; no allocation at runtime)
// ---------------------------------------------------------------------------
__device__ float g_h [(size_t)2 * CH6 * HWn];   // pconv output (attn h, then ffn h)
__device__ float g_h2[(size_t)2 * CH6 * HWn];   // dwconv output
__device__ float g_x1[(size_t)2 * DIM * HWn];   // x + attention branch
__device__ float g_gker[CH6 * 64];              // per-channel 8x8 conv kernel (irfft2 of fft_params)
__device__ int   g_isdelta[CH6];                // per-channel "kernel is delta" flag

// ---------------------------------------------------------------------------
// packed f32x2 helpers
// ---------------------------------------------------------------------------
__device__ __forceinline__ u64 pack2_dup(float a) {
    u64 r; asm("mov.b64 %0, {%1, %1};" : "=l"(r) : "f"(a)); return r;
}
__device__ __forceinline__ u64 fma2(u64 a, u64 b, u64 c) {
    u64 d; asm("fma.rn.f32x2 %0, %1, %2, %3;" : "=l"(d) : "l"(a), "l"(b), "l"(c)); return d;
}
__device__ __forceinline__ float2 unpack2(u64 v) {
    float2 f; asm("mov.b64 {%0, %1}, %2;" : "=f"(f.x), "=f"(f.y) : "l"(v)); return f;
}

// ---------------------------------------------------------------------------
// K0: per-channel FFN conv kernel g_c = irfft2(fft_params_c)  + delta flag
// grid: 384 blocks x 64 threads (thread = output position (x,y))
// ---------------------------------------------------------------------------
__global__ void k_prep(const float* __restrict__ fp /*[384][8][5]*/) {
    int c = blockIdx.x;
    int t = threadIdx.x;           // 0..63
    int x = t >> 3, y = t & 7;
    float s = 0.f;
    #pragma unroll
    for (int kx = 0; kx < 8; kx++) {
        #pragma unroll
        for (int ky = 0; ky < 8; ky++) {
            float Sv = (ky <= 4) ? fp[c * 40 + kx * 5 + ky]
                                 : fp[c * 40 + (((8 - kx) & 7) * 5) + (8 - ky)];
            int m = (kx * x + ky * y) & 7;
            s += Sv * cospif((float)m * 0.25f);   // cos(2*pi*m/8)
        }
    }
    s *= (1.f / 64.f);
    g_gker[c * 64 + t] = s;
    float target = (t == 0) ? 1.f : 0.f;
    int ok = __syncthreads_and(fabsf(s - target) <= 1e-5f);
    if (t == 0) g_isdelta[c] = ok;
}

// ---------------------------------------------------------------------------
// K1/K4: fused LayerNorm (per 64-float chunk) + 1x1 conv GEMM [384 x 64]
//        (+ optional per-channel 8x8 circular conv epilogue for the FFN path)
// grid: 2048 blocks (b*1024 + chunk), 512 threads
// shared: s_in 64x64 (16KB) + s_W 64x384 (96KB, reused as staging)
// ---------------------------------------------------------------------------
__global__ void __launch_bounds__(512)
k_ln_pconv(const float* __restrict__ xin,      // used when mode==0
           const float* __restrict__ nw,
           const float* __restrict__ nb,
           const float* __restrict__ Wmat,     // [384][64]
           int mode)                           // 0: attn (in=xin, no conv)  1: ffn (in=g_x1, conv epi)
{
    extern __shared__ float sh[];
    float* s_in = sh;                 // [ic][px]  64*64
    float* s_W  = sh + 64 * 64;       // [ic][oc]  64*384

    const float* in = (mode == 0) ? xin : g_x1;
    float* out = g_h;

    int tid = threadIdx.x;
    int b   = blockIdx.x >> 10;
    int ch  = blockIdx.x & 1023;
    size_t pxoff = (size_t)ch * 64;

    // stage weights transposed: s_W[ic*384+oc]
    for (int i = tid; i < CH6 * DIM; i += 512) {
        int oc = i >> 6, ic = i & 63;
        s_W[ic * CH6 + oc] = Wmat[i];
    }

    // LayerNorm: 16 warps x 4 rows; each row = one 64-float chunk of one channel
    int warp = tid >> 5, lane = tid & 31;
    #pragma unroll
    for (int r = 0; r < 4; r++) {
        int ic = warp * 4 + r;
        const float* xr = in + ((size_t)(b * DIM + ic)) * HWn + pxoff;
        float v0 = xr[lane * 2], v1 = xr[lane * 2 + 1];
        float s = v0 + v1;
        float q = v0 * v0 + v1 * v1;
        #pragma unroll
        for (int o = 16; o; o >>= 1) {
            s += __shfl_xor_sync(0xffffffffu, s, o);
            q += __shfl_xor_sync(0xffffffffu, q, o);
        }
        float mu  = s * (1.f / 64.f);
        float var = q * (1.f / 64.f) - mu * mu;
        float inv = rsqrtf(var + EPS);
        int j = lane * 2;
        float y0 = (v0 - mu) * inv * nw[j]     + nb[j];
        float y1 = (v1 - mu) * inv * nw[j + 1] + nb[j + 1];
        *(float2*)&s_in[ic * 64 + j] = make_float2(y0, y1);
    }
    __syncthreads();

    // GEMM: 512 threads; thread = 12 oc x 4 px; packed f32x2 over px pairs
    int ty = tid >> 4, tx = tid & 15;       // ty 0..31, tx 0..15
    int oc0 = ty * 12, px0 = tx * 4;
    u64 acc[12][2];
    #pragma unroll
    for (int o = 0; o < 12; o++) { acc[o][0] = 0ull; acc[o][1] = 0ull; }

    #pragma unroll 4
    for (int ic = 0; ic < 64; ic++) {
        u64 a0 = *(const u64*)&s_in[ic * 64 + px0];
        u64 a1 = *(const u64*)&s_in[ic * 64 + px0 + 2];
        const float* wr = &s_W[ic * CH6 + oc0];
        #pragma unroll
        for (int o = 0; o < 12; o++) {
            u64 w2 = pack2_dup(wr[o]);
            acc[o][0] = fma2(a0, w2, acc[o][0]);
            acc[o][1] = fma2(a1, w2, acc[o][1]);
        }
    }

    if (mode == 0) {
        #pragma unroll
        for (int o = 0; o < 12; o++) {
            float2 lo = unpack2(acc[o][0]), hi = unpack2(acc[o][1]);
            float4 v = make_float4(lo.x, lo.y, hi.x, hi.y);
            *(float4*)&out[((size_t)(b * CH6 + oc0 + o)) * HWn + pxoff + px0] = v;
        }
    } else {
        // stage GEMM result (overwrites s_W region), then per-channel circular conv
        __syncthreads();                 // everyone done reading s_W
        float* s_t = s_W;                // [c][p] 384*64
        #pragma unroll
        for (int o = 0; o < 12; o++) {
            float2 lo = unpack2(acc[o][0]), hi = unpack2(acc[o][1]);
            float4 v = make_float4(lo.x, lo.y, hi.x, hi.y);
            *(float4*)&s_t[(oc0 + o) * 64 + px0] = v;
        }
        __syncthreads();
        for (int idx = tid; idx < CH6 * 64; idx += 512) {
            int c = idx >> 6, p = idx & 63;
            float v;
            if (g_isdelta[c]) {
                v = s_t[idx];
            } else {
                int i = p >> 3, j = p & 7;
                const float* gk = &g_gker[c * 64];
                const float* tt = &s_t[c * 64];
                v = 0.f;
                for (int a = 0; a < 8; a++) {
                    int ri = ((i - a) & 7) * 8;
                    #pragma unroll
                    for (int bb = 0; bb < 8; bb++)
                        v += tt[ri + ((j - bb) & 7)] * gk[a * 8 + bb];
                }
            }
            out[((size_t)(b * CH6 + c)) * HWn + pxoff + p] = v;
        }
    }
}

// ---------------------------------------------------------------------------
// K2/K5: depthwise 3x3, SAME, per channel plane.  g_h -> g_h2
// grid: (16 row-blocks, 768 planes), 256 threads (one per column)
// ---------------------------------------------------------------------------
__global__ void __launch_bounds__(256)
k_dw(const float* __restrict__ wt /*[384][9]*/)
{
    __shared__ float s[18][Wimg];
    int plane = blockIdx.y;              // b*384 + c
    int c = plane % CH6;
    int r0 = blockIdx.x * 16;
    int col = threadIdx.x;
    const float* ip = g_h  + (size_t)plane * HWn;
    float*       op = g_h2 + (size_t)plane * HWn;

    #pragma unroll
    for (int r = 0; r < 18; r++) {
        int gr = r0 + r - 1;
        s[r][col] = (gr >= 0 && gr < Himg) ? ip[gr * Wimg + col] : 0.f;
    }
    float w[9];
    #pragma unroll
    for (int i = 0; i < 9; i++) w[i] = __ldg(&wt[c * 9 + i]);
    __syncthreads();

    #pragma unroll
    for (int r = 0; r < 16; r++) {
        float acc = 0.f;
        #pragma unroll
        for (int dr = 0; dr < 3; dr++) {
            const float* row = s[r + dr];
            float lft = (col > 0)        ? row[col - 1] : 0.f;
            float ctr = row[col];
            float rgt = (col < Wimg - 1) ? row[col + 1] : 0.f;
            acc += lft * w[dr * 3 + 0] + ctr * w[dr * 3 + 1] + rgt * w[dr * 3 + 2];
        }
        op[(r0 + r) * Wimg + col] = acc;
    }
}

// ---------------------------------------------------------------------------
// K3: attention tail, fused per 64-px chunk:
//     t = v * circconv8x8(q, k);  x1 = x + W2[64x128] @ t
// grid: 2048 blocks, 256 threads
// shared: s_q/s_k/s_t 128x64 each + s_w 128x64  -> 128KB
// ---------------------------------------------------------------------------
__global__ void __launch_bounds__(256)
k_attn(const float* __restrict__ x, const float* __restrict__ W2 /*[64][128]*/)
{
    extern __shared__ float sh[];
    float* s_q = sh;
    float* s_k = sh + 8192;
    float* s_t = sh + 16384;
    float* s_w = sh + 24576;

    int tid = threadIdx.x;
    int b   = blockIdx.x >> 10;
    int ch  = blockIdx.x & 1023;
    size_t base = (size_t)b * CH6 * HWn + (size_t)ch * 64;

    for (int i = tid; i < CH2 * 64; i += 256) {
        int c = i >> 6, p = i & 63;
        s_q[i] = g_h2[base + (size_t)c * HWn + p];
        s_k[i] = g_h2[base + (size_t)(CH2 + c) * HWn + p];
    }
    for (int i = tid; i < DIM * CH2; i += 256) {
        int oc = i >> 7, ic = i & 127;
        s_w[ic * 64 + oc] = W2[i];
    }
    __syncthreads();

    // circular conv: thread owns channel c = tid/2, rows i0..i0+3
    {
        int c  = tid >> 1;
        int i0 = (tid & 1) * 4;
        const float* q = &s_q[c * 64];
        const float* k = &s_k[c * 64];
        float kr[64];
        #pragma unroll
        for (int t2 = 0; t2 < 64; t2++) kr[t2] = k[t2];
        const float* vbase = g_h2 + base + (size_t)(2 * CH2 + c) * HWn;

        #pragma unroll 1
        for (int di = 0; di < 4; di++) {
            int i = i0 + di;
            float o[8];
            #pragma unroll
            for (int j = 0; j < 8; j++) o[j] = 0.f;
            #pragma unroll
            for (int a = 0; a < 8; a++) {
                const float* qr = &q[((i - a) & 7) * 8];
                float qv[8];
                #pragma unroll
                for (int j = 0; j < 8; j++) qv[j] = qr[j];
                #pragma unroll
                for (int bb = 0; bb < 8; bb++) {
                    float kv = kr[a * 8 + bb];
                    #pragma unroll
                    for (int j = 0; j < 8; j++)
                        o[j] += qv[(j - bb) & 7] * kv;
                }
            }
            const float* vrow = vbase + i * 8;
            #pragma unroll
            for (int j = 0; j < 8; j++)
                s_t[c * 64 + i * 8 + j] = o[j] * vrow[j];
        }
    }
    __syncthreads();

    // GEMM 64x128 @ 64 px, + residual x -> g_x1
    int ty = tid >> 4, tx = tid & 15;
    int oc0 = ty * 4, px0 = tx * 4;
    u64 acc[4][2];
    #pragma unroll
    for (int o = 0; o < 4; o++) { acc[o][0] = 0ull; acc[o][1] = 0ull; }
    #pragma unroll 4
    for (int ic = 0; ic < CH2; ic++) {
        u64 a0 = *(const u64*)&s_t[ic * 64 + px0];
        u64 a1 = *(const u64*)&s_t[ic * 64 + px0 + 2];
        const float* wr = &s_w[ic * 64 + oc0];
        #pragma unroll
        for (int o = 0; o < 4; o++) {
            u64 w2 = pack2_dup(wr[o]);
            acc[o][0] = fma2(a0, w2, acc[o][0]);
            acc[o][1] = fma2(a1, w2, acc[o][1]);
        }
    }
    #pragma unroll
    for (int o = 0; o < 4; o++) {
        size_t go = ((size_t)(b * DIM + oc0 + o)) * HWn + (size_t)ch * 64 + px0;
        float4 xv = *(const float4*)&x[go];
        float2 lo = unpack2(acc[o][0]), hi = unpack2(acc[o][1]);
        float4 r = make_float4(xv.x + lo.x, xv.y + lo.y, xv.z + hi.x, xv.w + hi.y);
        *(float4*)&g_x1[go] = r;
    }
}

// ---------------------------------------------------------------------------
// K6: FFN tail, fused per 64-px chunk:
//     t = gelu(h2[0:192]) * h2[192:384];  out = x1 + W3[64x192] @ t
// grid: 2048 blocks, 256 threads; shared: s_t 192x64 + s_w 192x64 -> 96KB
// ---------------------------------------------------------------------------
__global__ void __launch_bounds__(256)
k_ffn_out(const float* __restrict__ W3 /*[64][192]*/, float* __restrict__ dout)
{
    extern __shared__ float sh[];
    float* s_t = sh;
    float* s_w = sh + HID * 64;

    int tid = threadIdx.x;
    int b   = blockIdx.x >> 10;
    int ch  = blockIdx.x & 1023;
    size_t base = (size_t)b * CH6 * HWn + (size_t)ch * 64;

    for (int i = tid; i < HID * 64; i += 256) {
        int c = i >> 6, p = i & 63;
        float a  = g_h2[base + (size_t)c * HWn + p];
        float b2 = g_h2[base + (size_t)(HID + c) * HWn + p];
        float g  = 0.5f * a * (1.f + erff(a * 0.70710678118654752f));
        s_t[i] = g * b2;
    }
    for (int i = tid; i < DIM * HID; i += 256) {
        int oc = i / HID, ic = i % HID;
        s_w[ic * 64 + oc] = W3[i];
    }
    __syncthreads();

    int ty = tid >> 4, tx = tid & 15;
    int oc0 = ty * 4, px0 = tx * 4;
    u64 acc[4][2];
    #pragma unroll
    for (int o = 0; o < 4; o++) { acc[o][0] = 0ull; acc[o][1] = 0ull; }
    #pragma unroll 4
    for (int ic = 0; ic < HID; ic++) {
        u64 a0 = *(const u64*)&s_t[ic * 64 + px0];
        u64 a1 = *(const u64*)&s_t[ic * 64 + px0 + 2];
        const float* wr = &s_w[ic * 64 + oc0];
        #pragma unroll
        for (int o = 0; o < 4; o++) {
            u64 w2 = pack2_dup(wr[o]);
            acc[o][0] = fma2(a0, w2, acc[o][0]);
            acc[o][1] = fma2(a1, w2, acc[o][1]);
        }
    }
    #pragma unroll
    for (int o = 0; o < 4; o++) {
        size_t go = ((size_t)(b * DIM + oc0 + o)) * HWn + (size_t)ch * 64 + px0;
        float4 xv = *(const float4*)&g_x1[go];
        float2 lo = unpack2(acc[o][0]), hi = unpack2(acc[o][1]);
        float4 r = make_float4(xv.x + lo.x, xv.y + lo.y, xv.z + hi.x, xv.w + hi.y);
        *(float4*)&dout[go] = r;
    }
}

// ---------------------------------------------------------------------------
// launcher
// ---------------------------------------------------------------------------
extern "C" void kernel_launch(void* const* d_in, const int* in_sizes, int n_in,
                              void* d_out, int out_size)
{
    const float* x        = (const float*)d_in[0];
    const float* n1w      = (const float*)d_in[1];
    const float* n1b      = (const float*)d_in[2];
    const float* apin     = (const float*)d_in[3];
    const float* adw      = (const float*)d_in[4];
    const float* apout    = (const float*)d_in[5];
    const float* n2w      = (const float*)d_in[6];
    const float* n2b      = (const float*)d_in[7];
    const float* fpin     = (const float*)d_in[8];
    const float* fdw      = (const float*)d_in[9];
    const float* ffft     = (const float*)d_in[10];
    const float* fpout    = (const float*)d_in[11];
    float* out            = (float*)d_out;

    (void)in_sizes; (void)n_in; (void)out_size;

    static int attr_done = 0;
    // setting attributes is idempotent & deterministic; call every time
    cudaFuncSetAttribute(k_ln_pconv, cudaFuncAttributeMaxDynamicSharedMemorySize, 114688);
    cudaFuncSetAttribute(k_attn,     cudaFuncAttributeMaxDynamicSharedMemorySize, 131072);
    cudaFuncSetAttribute(k_ffn_out,  cudaFuncAttributeMaxDynamicSharedMemorySize,  98304);
    (void)attr_done;

    // K0: FFN spectral kernels + delta flags
    k_prep<<<CH6, 64>>>(ffft);

    // attention branch
    k_ln_pconv<<<2048, 512, 114688>>>(x, n1w, n1b, apin, /*mode=*/0);
    k_dw<<<dim3(16, 2 * CH6), 256>>>(adw);
    k_attn<<<2048, 256, 131072>>>(x, apout);

    // FFN branch
    k_ln_pconv<<<2048, 512, 114688>>>(x /*ignored*/, n2w, n2b, fpin, /*mode=*/1);
    k_dw<<<dim3(16, 2 * CH6), 256>>>(fdw);
    k_ffn_out<<<2048, 256, 98304>>>(fpout, out);
}

// round 4
// speedup vs baseline: 1.2849x; 1.2849x over previous
#include <cuda_runtime.h>
#include <math.h>

// ---------------------------------------------------------------------------
// Problem constants (fixed shapes from setup_inputs)
// ---------------------------------------------------------------------------
#define HWn   65536           // H*W = 256*256
#define Wimg  256
#define Himg  256
#define DIM   64
#define CH6   384             // 6*dim == 2*hidden (hidden=192)
#define CH2   128             // 2*dim (q/k/v channel count)
#define HID   192
#define EPS   1e-5f

typedef unsigned long long u64;

// ---------------------------------------------------------------------------
// Scratch (static device globals; no allocation at runtime)
// ---------------------------------------------------------------------------
__device__ float g_h [(size_t)2 * CH6 * HWn];   // pconv output
__device__ float g_h2[(size_t)2 * CH6 * HWn];   // dwconv output
__device__ float g_x1[(size_t)2 * DIM * HWn];   // x + attention branch
__device__ float g_gker[CH6 * 64];              // per-channel 8x8 conv kernel
__device__ int   g_isdelta[CH6];                // per-channel delta flag

// ---------------------------------------------------------------------------
// packed f32x2 helpers
// ---------------------------------------------------------------------------
__device__ __forceinline__ u64 pack2_dup(float a) {
    u64 r; asm("mov.b64 %0, {%1, %1};" : "=l"(r) : "f"(a)); return r;
}
__device__ __forceinline__ u64 fma2(u64 a, u64 b, u64 c) {
    u64 d; asm("fma.rn.f32x2 %0, %1, %2, %3;" : "=l"(d) : "l"(a), "l"(b), "l"(c)); return d;
}
__device__ __forceinline__ float2 unpack2(u64 v) {
    float2 f; asm("mov.b64 {%0, %1}, %2;" : "=f"(f.x), "=f"(f.y) : "l"(v)); return f;
}

// ---------------------------------------------------------------------------
// K0: per-channel FFN conv kernel g_c = irfft2(fft_params_c)  + delta flag
// ---------------------------------------------------------------------------
__global__ void k_prep(const float* __restrict__ fp /*[384][8][5]*/) {
    int c = blockIdx.x;
    int t = threadIdx.x;           // 0..63
    int x = t >> 3, y = t & 7;
    float s = 0.f;
    #pragma unroll
    for (int kx = 0; kx < 8; kx++) {
        #pragma unroll
        for (int ky = 0; ky < 8; ky++) {
            float Sv = (ky <= 4) ? fp[c * 40 + kx * 5 + ky]
                                 : fp[c * 40 + (((8 - kx) & 7) * 5) + (8 - ky)];
            int m = (kx * x + ky * y) & 7;
            s += Sv * cospif((float)m * 0.25f);
        }
    }
    s *= (1.f / 64.f);
    g_gker[c * 64 + t] = s;
    float target = (t == 0) ? 1.f : 0.f;
    int ok = __syncthreads_and(fabsf(s - target) <= 1e-5f);
    if (t == 0) g_isdelta[c] = ok;
}

// ---------------------------------------------------------------------------
// K1/K4: fused LayerNorm (per 64-float chunk) + 1x1 conv GEMM [384 x 64]
//        (+ optional per-channel 8x8 circular conv epilogue for the FFN path)
// grid: 2048 blocks, 1024 threads (full SM occupancy)
// shared: s_in 64x64 (16KB) + s_W 384x64 contiguous copy (96KB)
// ---------------------------------------------------------------------------
__global__ void __launch_bounds__(1024, 1)
k_ln_pconv(const float* __restrict__ xin,
           const float* __restrict__ nw,
           const float* __restrict__ nb,
           const float* __restrict__ Wmat,     // [384][64]
           int mode)                           // 0: attn (in=xin)  1: ffn (in=g_x1, conv epi)
{
    extern __shared__ float sh[];
    float* s_in = sh;                 // [ic][px]  64*64
    float* s_W  = sh + 64 * 64;       // contiguous copy of Wmat [oc][ic]

    const float* in = (mode == 0) ? xin : g_x1;
    float* out = g_h;

    int tid = threadIdx.x;
    int b   = blockIdx.x >> 10;
    int ch  = blockIdx.x & 1023;
    size_t pxoff = (size_t)ch * 64;

    // stage weights: plain contiguous copy (coalesced, conflict-free)
    for (int i = tid; i < CH6 * DIM; i += 1024)
        s_W[i] = Wmat[i];

    // LayerNorm: 32 warps x 2 rows
    int warp = tid >> 5, lane = tid & 31;
    #pragma unroll
    for (int r = 0; r < 2; r++) {
        int ic = warp * 2 + r;
        const float* xr = in + ((size_t)(b * DIM + ic)) * HWn + pxoff;
        float v0 = xr[lane * 2], v1 = xr[lane * 2 + 1];
        float s = v0 + v1;
        float q = v0 * v0 + v1 * v1;
        #pragma unroll
        for (int o = 16; o; o >>= 1) {
            s += __shfl_xor_sync(0xffffffffu, s, o);
            q += __shfl_xor_sync(0xffffffffu, q, o);
        }
        float mu  = s * (1.f / 64.f);
        float var = q * (1.f / 64.f) - mu * mu;
        float inv = rsqrtf(var + EPS);
        int j = lane * 2;
        float y0 = (v0 - mu) * inv * nw[j]     + nb[j];
        float y1 = (v1 - mu) * inv * nw[j + 1] + nb[j + 1];
        *(float2*)&s_in[ic * 64 + j] = make_float2(y0, y1);
    }
    __syncthreads();

    // GEMM: thread = 6 oc x 4 px
    int ty = tid >> 4, tx = tid & 15;       // ty 0..63, tx 0..15
    int oc0 = ty * 6, px0 = tx * 4;
    u64 acc[6][2];
    #pragma unroll
    for (int o = 0; o < 6; o++) { acc[o][0] = 0ull; acc[o][1] = 0ull; }

    #pragma unroll 4
    for (int ic = 0; ic < 64; ic++) {
        u64 a0 = *(const u64*)&s_in[ic * 64 + px0];
        u64 a1 = *(const u64*)&s_in[ic * 64 + px0 + 2];
        #pragma unroll
        for (int o = 0; o < 6; o++) {
            u64 w2 = pack2_dup(s_W[(oc0 + o) * 64 + ic]);   // broadcast read
            acc[o][0] = fma2(a0, w2, acc[o][0]);
            acc[o][1] = fma2(a1, w2, acc[o][1]);
        }
    }

    if (mode == 0) {
        #pragma unroll
        for (int o = 0; o < 6; o++) {
            float2 lo = unpack2(acc[o][0]), hi = unpack2(acc[o][1]);
            float4 v = make_float4(lo.x, lo.y, hi.x, hi.y);
            *(float4*)&out[((size_t)(b * CH6 + oc0 + o)) * HWn + pxoff + px0] = v;
        }
    } else {
        __syncthreads();                 // everyone done reading s_W
        float* s_t = s_W;                // overlay: [c][p] 384*64
        #pragma unroll
        for (int o = 0; o < 6; o++) {
            float2 lo = unpack2(acc[o][0]), hi = unpack2(acc[o][1]);
            float4 v = make_float4(lo.x, lo.y, hi.x, hi.y);
            *(float4*)&s_t[(oc0 + o) * 64 + px0] = v;
        }
        __syncthreads();
        for (int idx = tid; idx < CH6 * 64; idx += 1024) {
            int c = idx >> 6, p = idx & 63;
            float v;
            if (g_isdelta[c]) {
                v = s_t[idx];
            } else {
                int i = p >> 3, j = p & 7;
                const float* gk = &g_gker[c * 64];
                const float* tt = &s_t[c * 64];
                v = 0.f;
                for (int a = 0; a < 8; a++) {
                    int ri = ((i - a) & 7) * 8;
                    #pragma unroll
                    for (int bb = 0; bb < 8; bb++)
                        v += tt[ri + ((j - bb) & 7)] * gk[a * 8 + bb];
                }
            }
            out[((size_t)(b * CH6 + c)) * HWn + pxoff + p] = v;
        }
    }
}

// ---------------------------------------------------------------------------
// K2/K5: depthwise 3x3, SAME.  g_h -> g_h2
// grid: (8 row-blocks, 768 planes), 256 threads (one per column), 32 rows/block
// ---------------------------------------------------------------------------
__global__ void __launch_bounds__(256)
k_dw(const float* __restrict__ wt /*[384][9]*/)
{
    __shared__ float s[34][Wimg];
    int plane = blockIdx.y;              // b*384 + c
    int c = plane % CH6;
    int r0 = blockIdx.x * 32;
    int col = threadIdx.x;
    const float* ip = g_h  + (size_t)plane * HWn;
    float*       op = g_h2 + (size_t)plane * HWn;

    #pragma unroll
    for (int r = 0; r < 34; r++) {
        int gr = r0 + r - 1;
        s[r][col] = (gr >= 0 && gr < Himg) ? ip[gr * Wimg + col] : 0.f;
    }
    float w[9];
    #pragma unroll
    for (int i = 0; i < 9; i++) w[i] = __ldg(&wt[c * 9 + i]);
    __syncthreads();

    #pragma unroll 8
    for (int r = 0; r < 32; r++) {
        float acc = 0.f;
        #pragma unroll
        for (int dr = 0; dr < 3; dr++) {
            const float* row = s[r + dr];
            float lft = (col > 0)        ? row[col - 1] : 0.f;
            float ctr = row[col];
            float rgt = (col < Wimg - 1) ? row[col + 1] : 0.f;
            acc += lft * w[dr * 3 + 0] + ctr * w[dr * 3 + 1] + rgt * w[dr * 3 + 2];
        }
        op[(r0 + r) * Wimg + col] = acc;
    }
}

// ---------------------------------------------------------------------------
// K3: attention tail, fused per 64-px chunk:
//     t = v * circconv8x8(q, k);  x1 = x + W2[64x128] @ t
// grid: 2048 blocks, 256 threads; shared: s_q + s_k + s_w = 96KB (2 blocks/SM)
// ---------------------------------------------------------------------------
__global__ void __launch_bounds__(256)
k_attn(const float* __restrict__ x, const float* __restrict__ W2 /*[64][128]*/)
{
    extern __shared__ float sh[];
    float* s_q = sh;            // 128*64
    float* s_k = sh + 8192;     // 128*64
    float* s_w = sh + 16384;    // 64*128 contiguous copy of W2
    float* s_t = s_q;           // overlay after conv

    int tid = threadIdx.x;
    int b   = blockIdx.x >> 10;
    int ch  = blockIdx.x & 1023;
    size_t base = (size_t)b * CH6 * HWn + (size_t)ch * 64;

    for (int i = tid; i < CH2 * 64; i += 256) {
        int c = i >> 6, p = i & 63;
        s_q[i] = g_h2[base + (size_t)c * HWn + p];
        s_k[i] = g_h2[base + (size_t)(CH2 + c) * HWn + p];
    }
    for (int i = tid; i < DIM * CH2; i += 256)
        s_w[i] = W2[i];
    __syncthreads();

    // circular conv: thread owns channel c = tid/2, rows i0..i0+3; k read from
    // shared per-a (broadcast across the channel's 2 threads) -> no reg spills
    int c  = tid >> 1;
    int i0 = (tid & 1) * 4;
    float o[4][8];
    #pragma unroll
    for (int di = 0; di < 4; di++)
        #pragma unroll
        for (int j = 0; j < 8; j++) o[di][j] = 0.f;
    {
        const float* qb = &s_q[c * 64];
        const float* kb = &s_k[c * 64];
        #pragma unroll 2
        for (int a = 0; a < 8; a++) {
            float kv[8];
            *(float4*)&kv[0] = *(const float4*)&kb[a * 8];
            *(float4*)&kv[4] = *(const float4*)&kb[a * 8 + 4];
            #pragma unroll
            for (int di = 0; di < 4; di++) {
                int ri = ((i0 + di - a) & 7) * 8;
                float qv[8];
                *(float4*)&qv[0] = *(const float4*)&qb[ri];
                *(float4*)&qv[4] = *(const float4*)&qb[ri + 4];
                #pragma unroll
                for (int bb = 0; bb < 8; bb++) {
                    float kvv = kv[bb];
                    #pragma unroll
                    for (int j = 0; j < 8; j++)
                        o[di][j] += qv[(j - bb) & 7] * kvv;
                }
            }
        }
    }
    // multiply by v (global read; s_q still intact, no hazard yet)
    {
        const float* vbase = g_h2 + base + (size_t)(2 * CH2 + c) * HWn;
        #pragma unroll
        for (int di = 0; di < 4; di++) {
            float4 v0 = *(const float4*)&vbase[(i0 + di) * 8];
            float4 v1 = *(const float4*)&vbase[(i0 + di) * 8 + 4];
            o[di][0] *= v0.x; o[di][1] *= v0.y; o[di][2] *= v0.z; o[di][3] *= v0.w;
            o[di][4] *= v1.x; o[di][5] *= v1.y; o[di][6] *= v1.z; o[di][7] *= v1.w;
        }
    }
    __syncthreads();   // all conv reads of s_q done
    #pragma unroll
    for (int di = 0; di < 4; di++) {
        *(float4*)&s_t[c * 64 + (i0 + di) * 8]     = *(float4*)&o[di][0];
        *(float4*)&s_t[c * 64 + (i0 + di) * 8 + 4] = *(float4*)&o[di][4];
    }
    __syncthreads();

    // GEMM 64x128 @ 64 px (+residual): thread = 2 oc x 8 px
    int ty = tid >> 3, tx = tid & 7;
    int oc0 = ty * 2, px0 = tx * 8;
    u64 acc[2][4];
    #pragma unroll
    for (int oo = 0; oo < 2; oo++)
        #pragma unroll
        for (int pp = 0; pp < 4; pp++) acc[oo][pp] = 0ull;
    #pragma unroll 4
    for (int ic = 0; ic < CH2; ic++) {
        u64 a0 = *(const u64*)&s_t[ic * 64 + px0];
        u64 a1 = *(const u64*)&s_t[ic * 64 + px0 + 2];
        u64 a2 = *(const u64*)&s_t[ic * 64 + px0 + 4];
        u64 a3 = *(const u64*)&s_t[ic * 64 + px0 + 6];
        #pragma unroll
        for (int oo = 0; oo < 2; oo++) {
            u64 w2 = pack2_dup(s_w[(oc0 + oo) * CH2 + ic]);
            acc[oo][0] = fma2(a0, w2, acc[oo][0]);
            acc[oo][1] = fma2(a1, w2, acc[oo][1]);
            acc[oo][2] = fma2(a2, w2, acc[oo][2]);
            acc[oo][3] = fma2(a3, w2, acc[oo][3]);
        }
    }
    #pragma unroll
    for (int oo = 0; oo < 2; oo++) {
        size_t go = ((size_t)(b * DIM + oc0 + oo)) * HWn + (size_t)ch * 64 + px0;
        #pragma unroll
        for (int h = 0; h < 2; h++) {
            float4 xv = *(const float4*)&x[go + h * 4];
            float2 lo = unpack2(acc[oo][h * 2]), hi = unpack2(acc[oo][h * 2 + 1]);
            float4 r = make_float4(xv.x + lo.x, xv.y + lo.y, xv.z + hi.x, xv.w + hi.y);
            *(float4*)&g_x1[go + h * 4] = r;
        }
    }
}

// ---------------------------------------------------------------------------
// K6: FFN tail, fused per 64-px chunk:
//     t = gelu(h2[0:192]) * h2[192:384];  out = x1 + W3[64x192] @ t
// grid: 2048 blocks, 256 threads; shared: s_t 192x64 + s_w 64x192 = 96KB
// ---------------------------------------------------------------------------
__global__ void __launch_bounds__(256)
k_ffn_out(const float* __restrict__ W3 /*[64][192]*/, float* __restrict__ dout)
{
    extern __shared__ float sh[];
    float* s_t = sh;              // [c][p] 192*64
    float* s_w = sh + HID * 64;   // contiguous copy of W3

    int tid = threadIdx.x;
    int b   = blockIdx.x >> 10;
    int ch  = blockIdx.x & 1023;
    size_t base = (size_t)b * CH6 * HWn + (size_t)ch * 64;

    for (int i = tid; i < HID * 64; i += 256) {
        int c = i >> 6, p = i & 63;
        float a  = g_h2[base + (size_t)c * HWn + p];
        float b2 = g_h2[base + (size_t)(HID + c) * HWn + p];
        float g  = 0.5f * a * (1.f + erff(a * 0.70710678118654752f));
        s_t[i] = g * b2;
    }
    for (int i = tid; i < DIM * HID; i += 256)
        s_w[i] = W3[i];
    __syncthreads();

    // GEMM 64x192 @ 64 px: thread = 2 oc x 8 px
    int ty = tid >> 3, tx = tid & 7;
    int oc0 = ty * 2, px0 = tx * 8;
    u64 acc[2][4];
    #pragma unroll
    for (int oo = 0; oo < 2; oo++)
        #pragma unroll
        for (int pp = 0; pp < 4; pp++) acc[oo][pp] = 0ull;
    #pragma unroll 4
    for (int ic = 0; ic < HID; ic++) {
        u64 a0 = *(const u64*)&s_t[ic * 64 + px0];
        u64 a1 = *(const u64*)&s_t[ic * 64 + px0 + 2];
        u64 a2 = *(const u64*)&s_t[ic * 64 + px0 + 4];
        u64 a3 = *(const u64*)&s_t[ic * 64 + px0 + 6];
        #pragma unroll
        for (int oo = 0; oo < 2; oo++) {
            u64 w2 = pack2_dup(s_w[(oc0 + oo) * HID + ic]);
            acc[oo][0] = fma2(a0, w2, acc[oo][0]);
            acc[oo][1] = fma2(a1, w2, acc[oo][1]);
            acc[oo][2] = fma2(a2, w2, acc[oo][2]);
            acc[oo][3] = fma2(a3, w2, acc[oo][3]);
        }
    }
    #pragma unroll
    for (int oo = 0; oo < 2; oo++) {
        size_t go = ((size_t)(b * DIM + oc0 + oo)) * HWn + (size_t)ch * 64 + px0;
        #pragma unroll
        for (int h = 0; h < 2; h++) {
            float4 xv = *(const float4*)&g_x1[go + h * 4];
            float2 lo = unpack2(acc[oo][h * 2]), hi = unpack2(acc[oo][h * 2 + 1]);
            float4 r = make_float4(xv.x + lo.x, xv.y + lo.y, xv.z + hi.x, xv.w + hi.y);
            *(float4*)&dout[go + h * 4] = r;
        }
    }
}

// ---------------------------------------------------------------------------
// launcher
// ---------------------------------------------------------------------------
extern "C" void kernel_launch(void* const* d_in, const int* in_sizes, int n_in,
                              void* d_out, int out_size)
{
    const float* x     = (const float*)d_in[0];
    const float* n1w   = (const float*)d_in[1];
    const float* n1b   = (const float*)d_in[2];
    const float* apin  = (const float*)d_in[3];
    const float* adw   = (const float*)d_in[4];
    const float* apout = (const float*)d_in[5];
    const float* n2w   = (const float*)d_in[6];
    const float* n2b   = (const float*)d_in[7];
    const float* fpin  = (const float*)d_in[8];
    const float* fdw   = (const float*)d_in[9];
    const float* ffft  = (const float*)d_in[10];
    const float* fpout = (const float*)d_in[11];
    float* out         = (float*)d_out;

    (void)in_sizes; (void)n_in; (void)out_size;

    cudaFuncSetAttribute(k_ln_pconv, cudaFuncAttributeMaxDynamicSharedMemorySize, 114688);
    cudaFuncSetAttribute(k_attn,     cudaFuncAttributeMaxDynamicSharedMemorySize,  98304);
    cudaFuncSetAttribute(k_ffn_out,  cudaFuncAttributeMaxDynamicSharedMemorySize,  98304);

    // K0: FFN spectral kernels + delta flags
    k_prep<<<CH6, 64>>>(ffft);

    // attention branch
    k_ln_pconv<<<2048, 1024, 114688>>>(x, n1w, n1b, apin, /*mode=*/0);
    k_dw<<<dim3(8, 2 * CH6), 256>>>(adw);
    k_attn<<<2048, 256, 98304>>>(x, apout);

    // FFN branch
    k_ln_pconv<<<2048, 1024, 114688>>>(x /*ignored*/, n2w, n2b, fpin, /*mode=*/1);
    k_dw<<<dim3(8, 2 * CH6), 256>>>(fdw);
    k_ffn_out<<<2048, 256, 98304>>>(fpout, out);
}

// round 5
// speedup vs baseline: 1.5603x; 1.2144x over previous
#include <cuda_runtime.h>
#include <math.h>

#define HWn   65536
#define Wimg  256
#define Himg  256
#define DIM   64
#define CH6   384
#define CH2   128
#define HID   192
#define EPS   1e-5f
#define STRK  72
#define STRM  68

typedef unsigned int u32;

__device__ float g_h [(size_t)2 * CH6 * HWn];
__device__ float g_h2[(size_t)2 * CH6 * HWn];
__device__ float g_x1[(size_t)2 * DIM * HWn];
__device__ float g_gker[CH6 * 64];
__device__ int   g_isdelta[CH6];

__device__ __forceinline__ u32 to_tf32(float f) {
    u32 r; asm("cvt.rna.tf32.f32 %0, %1;" : "=r"(r) : "f"(f)); return r;
}
__device__ __forceinline__ void mma_tf32(float d[4], u32 a0, u32 a1, u32 a2, u32 a3,
                                         u32 b0, u32 b1) {
    asm volatile(
        "mma.sync.aligned.m16n8k8.row.col.f32.tf32.tf32.f32 "
        "{%0,%1,%2,%3}, {%4,%5,%6,%7}, {%8,%9}, {%0,%1,%2,%3};"
        : "+f"(d[0]), "+f"(d[1]), "+f"(d[2]), "+f"(d[3])
        : "r"(a0), "r"(a1), "r"(a2), "r"(a3), "r"(b0), "r"(b1));
}

__global__ void k_prep(const float* __restrict__ fp) {
    int c = blockIdx.x;
    int t = threadIdx.x;
    int x = t >> 3, y = t & 7;
    float s = 0.f;
    #pragma unroll
    for (int kx = 0; kx < 8; kx++) {
        #pragma unroll
        for (int ky = 0; ky < 8; ky++) {
            float Sv = (ky <= 4) ? fp[c * 40 + kx * 5 + ky]
                                 : fp[c * 40 + (((8 - kx) & 7) * 5) + (8 - ky)];
            int m = (kx * x + ky * y) & 7;
            s += Sv * cospif((float)m * 0.25f);
        }
    }
    s *= (1.f / 64.f);
    g_gker[c * 64 + t] = s;
    float target = (t == 0) ? 1.f : 0.f;
    int ok = __syncthreads_and(fabsf(s - target) <= 1e-5f);
    if (t == 0) g_isdelta[c] = ok;
}

// ---- fused LayerNorm + 1x1 conv [384x64] via tf32 mma (+conv epilogue mode 1)
__global__ void __launch_bounds__(512, 1)
k_ln_pconv(const float* __restrict__ xin,
           const float* __restrict__ nw,
           const float* __restrict__ nb,
           const float* __restrict__ Wmat,
           int mode)
{
    extern __shared__ float sh[];
    float* s_in = sh;                       // [64ic][STRK]
    float* s_W  = sh + 64 * STRK;           // [384oc][STRM]
    u32*   s_in_u = (u32*)s_in;
    u32*   s_W_u  = (u32*)s_W;

    const float* in = (mode == 0) ? xin : g_x1;

    int tid = threadIdx.x;
    int b   = blockIdx.x >> 10;
    int ch  = blockIdx.x & 1023;
    size_t pxoff = (size_t)ch * 64;

    for (int i = tid; i < CH6 * DIM; i += 512) {
        int oc = i >> 6, ic = i & 63;
        s_W_u[oc * STRM + ic] = to_tf32(Wmat[i]);
    }

    int warp = tid >> 5, lane = tid & 31;
    #pragma unroll
    for (int r = 0; r < 4; r++) {
        int ic = warp * 4 + r;
        const float* xr = in + ((size_t)(b * DIM + ic)) * HWn + pxoff;
        float v0 = xr[lane * 2], v1 = xr[lane * 2 + 1];
        float s = v0 + v1;
        float q = v0 * v0 + v1 * v1;
        #pragma unroll
        for (int o = 16; o; o >>= 1) {
            s += __shfl_xor_sync(0xffffffffu, s, o);
            q += __shfl_xor_sync(0xffffffffu, q, o);
        }
        float mu  = s * (1.f / 64.f);
        float var = q * (1.f / 64.f) - mu * mu;
        float inv = rsqrtf(var + EPS);
        int j = lane * 2;
        float y0 = (v0 - mu) * inv * nw[j]     + nb[j];
        float y1 = (v1 - mu) * inv * nw[j + 1] + nb[j + 1];
        uint2 pk = make_uint2(to_tf32(y0), to_tf32(y1));
        *(uint2*)&s_in_u[ic * STRK + j] = pk;
    }
    __syncthreads();

    int g  = lane >> 2;
    int q4 = lane & 3;
    float dhold[2][8][4];      // mode-1 register staging (2 slabs x 8 n-tiles)

    for (int s = warp; s < 24; s += 16) {
        int m0 = s * 16;
        float d[8][4];
        #pragma unroll
        for (int nt = 0; nt < 8; nt++)
            #pragma unroll
            for (int e = 0; e < 4; e++) d[nt][e] = 0.f;

        #pragma unroll
        for (int ks = 0; ks < 8; ks++) {
            int k0 = ks * 8;
            u32 a0 = s_W_u[(m0 + g) * STRM + k0 + q4];
            u32 a1 = s_W_u[(m0 + g + 8) * STRM + k0 + q4];
            u32 a2 = s_W_u[(m0 + g) * STRM + k0 + q4 + 4];
            u32 a3 = s_W_u[(m0 + g + 8) * STRM + k0 + q4 + 4];
            #pragma unroll
            for (int nt = 0; nt < 8; nt++) {
                int n = nt * 8;
                u32 b0 = s_in_u[(k0 + q4) * STRK + n + g];
                u32 b1 = s_in_u[(k0 + q4 + 4) * STRK + n + g];
                mma_tf32(d[nt], a0, a1, a2, a3, b0, b1);
            }
        }

        if (mode == 0) {
            #pragma unroll
            for (int nt = 0; nt < 8; nt++) {
                int px = nt * 8 + q4 * 2;
                *(float2*)&g_h[((size_t)(b * CH6 + m0 + g)) * HWn + pxoff + px] =
                    make_float2(d[nt][0], d[nt][1]);
                *(float2*)&g_h[((size_t)(b * CH6 + m0 + g + 8)) * HWn + pxoff + px] =
                    make_float2(d[nt][2], d[nt][3]);
            }
        } else {
            int slot = (s >= 16) ? 1 : 0;
            #pragma unroll
            for (int nt = 0; nt < 8; nt++)
                #pragma unroll
                for (int e = 0; e < 4; e++)
                    dhold[slot][nt][e] = d[nt][e];
        }
    }

    if (mode == 1) {
        __syncthreads();               // all mma reads done
        float* s_stage = s_W;          // overlay: [oc][px] 384*64
        for (int slot = 0; slot < 2; slot++) {
            int s = warp + slot * 16;
            if (s >= 24) break;
            int m0 = s * 16;
            #pragma unroll
            for (int nt = 0; nt < 8; nt++) {
                int px = nt * 8 + q4 * 2;
                *(float2*)&s_stage[(m0 + g) * 64 + px] =
                    make_float2(dhold[slot][nt][0], dhold[slot][nt][1]);
                *(float2*)&s_stage[(m0 + g + 8) * 64 + px] =
                    make_float2(dhold[slot][nt][2], dhold[slot][nt][3]);
            }
        }
        __syncthreads();
        for (int idx = tid; idx < CH6 * 64; idx += 512) {
            int c = idx >> 6, p = idx & 63;
            float v;
            if (g_isdelta[c]) {
                v = s_stage[idx];
            } else {
                int i = p >> 3, j = p & 7;
                const float* gk = &g_gker[c * 64];
                const float* tt = &s_stage[c * 64];
                v = 0.f;
                for (int a = 0; a < 8; a++) {
                    int ri = ((i - a) & 7) * 8;
                    #pragma unroll
                    for (int bb = 0; bb < 8; bb++)
                        v += tt[ri + ((j - bb) & 7)] * gk[a * 8 + bb];
                }
            }
            g_h[((size_t)(b * CH6 + c)) * HWn + pxoff + p] = v;
        }
    }
}

__global__ void __launch_bounds__(256)
k_dw(const float* __restrict__ wt)
{
    __shared__ float s[34][Wimg];
    int plane = blockIdx.y;
    int c = plane % CH6;
    int r0 = blockIdx.x * 32;
    int col = threadIdx.x;
    const float* ip = g_h  + (size_t)plane * HWn;
    float*       op = g_h2 + (size_t)plane * HWn;

    #pragma unroll
    for (int r = 0; r < 34; r++) {
        int gr = r0 + r - 1;
        s[r][col] = (gr >= 0 && gr < Himg) ? ip[gr * Wimg + col] : 0.f;
    }
    float w[9];
    #pragma unroll
    for (int i = 0; i < 9; i++) w[i] = __ldg(&wt[c * 9 + i]);
    __syncthreads();

    #pragma unroll 8
    for (int r = 0; r < 32; r++) {
        float acc = 0.f;
        #pragma unroll
        for (int dr = 0; dr < 3; dr++) {
            const float* row = s[r + dr];
            float lft = (col > 0)        ? row[col - 1] : 0.f;
            float ctr = row[col];
            float rgt = (col < Wimg - 1) ? row[col + 1] : 0.f;
            acc += lft * w[dr * 3 + 0] + ctr * w[dr * 3 + 1] + rgt * w[dr * 3 + 2];
        }
        op[(r0 + r) * Wimg + col] = acc;
    }
}

__global__ void __launch_bounds__(256)
k_attn(const float* __restrict__ x, const float* __restrict__ W2)
{
    extern __shared__ float sh[];
    u32*   s_w_u = (u32*)sh;                  // [128ic][STRK]
    float* s_q   = sh + 9216;
    float* s_k   = sh + 17408;
    u32*   s_t_u = (u32*)(sh + 9216);         // overlays q,k

    int tid = threadIdx.x;
    int b   = blockIdx.x >> 10;
    int ch  = blockIdx.x & 1023;
    size_t base = (size_t)b * CH6 * HWn + (size_t)ch * 64;

    for (int i = tid; i < DIM * CH2; i += 256) {
        int oc = i >> 7, ic = i & 127;
        s_w_u[ic * STRK + oc] = to_tf32(W2[i]);
    }
    for (int i = tid; i < CH2 * 64; i += 256) {
        int c = i >> 6, p = i & 63;
        s_q[i] = g_h2[base + (size_t)c * HWn + p];
        s_k[i] = g_h2[base + (size_t)(CH2 + c) * HWn + p];
    }
    __syncthreads();

    int c  = tid >> 1;
    int i0 = (tid & 1) * 4;
    float o[4][8];
    #pragma unroll
    for (int di = 0; di < 4; di++)
        #pragma unroll
        for (int j = 0; j < 8; j++) o[di][j] = 0.f;
    {
        const float* qb = &s_q[c * 64];
        const float* kb = &s_k[c * 64];
        #pragma unroll 2
        for (int a = 0; a < 8; a++) {
            float kv[8];
            *(float4*)&kv[0] = *(const float4*)&kb[a * 8];
            *(float4*)&kv[4] = *(const float4*)&kb[a * 8 + 4];
            #pragma unroll
            for (int di = 0; di < 4; di++) {
                int ri = ((i0 + di - a) & 7) * 8;
                float qv[8];
                *(float4*)&qv[0] = *(const float4*)&qb[ri];
                *(float4*)&qv[4] = *(const float4*)&qb[ri + 4];
                #pragma unroll
                for (int bb = 0; bb < 8; bb++) {
                    float kvv = kv[bb];
                    #pragma unroll
                    for (int j = 0; j < 8; j++)
                        o[di][j] += qv[(j - bb) & 7] * kvv;
                }
            }
        }
    }
    {
        const float* vbase = g_h2 + base + (size_t)(2 * CH2 + c) * HWn;
        #pragma unroll
        for (int di = 0; di < 4; di++) {
            float4 v0 = *(const float4*)&vbase[(i0 + di) * 8];
            float4 v1 = *(const float4*)&vbase[(i0 + di) * 8 + 4];
            o[di][0] *= v0.x; o[di][1] *= v0.y; o[di][2] *= v0.z; o[di][3] *= v0.w;
            o[di][4] *= v1.x; o[di][5] *= v1.y; o[di][6] *= v1.z; o[di][7] *= v1.w;
        }
    }
    __syncthreads();
    #pragma unroll
    for (int di = 0; di < 4; di++) {
        uint4 p0 = make_uint4(to_tf32(o[di][0]), to_tf32(o[di][1]),
                              to_tf32(o[di][2]), to_tf32(o[di][3]));
        uint4 p1 = make_uint4(to_tf32(o[di][4]), to_tf32(o[di][5]),
                              to_tf32(o[di][6]), to_tf32(o[di][7]));
        *(uint4*)&s_t_u[c * STRK + (i0 + di) * 8]     = p0;
        *(uint4*)&s_t_u[c * STRK + (i0 + di) * 8 + 4] = p1;
    }
    __syncthreads();

    int warp = tid >> 5, lane = tid & 31;
    int g = lane >> 2, q4 = lane & 3;
    int m0 = (warp & 3) * 16, n0 = (warp >> 2) * 32;

    float d[4][4];
    #pragma unroll
    for (int nt = 0; nt < 4; nt++)
        #pragma unroll
        for (int e = 0; e < 4; e++) d[nt][e] = 0.f;

    #pragma unroll 4
    for (int ks = 0; ks < 16; ks++) {
        int k0 = ks * 8;
        u32 a0 = s_t_u[(k0 + q4) * STRK + m0 + g];
        u32 a1 = s_t_u[(k0 + q4) * STRK + m0 + g + 8];
        u32 a2 = s_t_u[(k0 + q4 + 4) * STRK + m0 + g];
        u32 a3 = s_t_u[(k0 + q4 + 4) * STRK + m0 + g + 8];
        #pragma unroll
        for (int nt = 0; nt < 4; nt++) {
            int n = n0 + nt * 8;
            u32 b0 = s_w_u[(k0 + q4) * STRK + n + g];
            u32 b1 = s_w_u[(k0 + q4 + 4) * STRK + n + g];
            mma_tf32(d[nt], a0, a1, a2, a3, b0, b1);
        }
    }

    #pragma unroll
    for (int nt = 0; nt < 4; nt++) {
        int oc = n0 + nt * 8 + q4 * 2;
        int px = m0 + g;
        size_t a00 = ((size_t)(b * DIM + oc)) * HWn + (size_t)ch * 64;
        size_t a01 = a00 + HWn;
        g_x1[a00 + px]     = x[a00 + px]     + d[nt][0];
        g_x1[a01 + px]     = x[a01 + px]     + d[nt][1];
        g_x1[a00 + px + 8] = x[a00 + px + 8] + d[nt][2];
        g_x1[a01 + px + 8] = x[a01 + px + 8] + d[nt][3];
    }
}

__global__ void __launch_bounds__(256)
k_ffn_out(const float* __restrict__ W3, float* __restrict__ dout)
{
    extern __shared__ float sh[];
    u32* s_w_u = (u32*)sh;
    u32* s_t_u = (u32*)(sh + HID * STRK);

    int tid = threadIdx.x;
    int b   = blockIdx.x >> 10;
    int ch  = blockIdx.x & 1023;
    size_t base = (size_t)b * CH6 * HWn + (size_t)ch * 64;

    for (int i = tid; i < DIM * HID; i += 256) {
        int oc = i / HID, ic = i % HID;
        s_w_u[ic * STRK + oc] = to_tf32(W3[i]);
    }
    for (int i = tid; i < HID * 64; i += 256) {
        int c = i >> 6, p = i & 63;
        float a  = g_h2[base + (size_t)c * HWn + p];
        float b2 = g_h2[base + (size_t)(HID + c) * HWn + p];
        float ge = 0.5f * a * (1.f + erff(a * 0.70710678118654752f));
        s_t_u[c * STRK + p] = to_tf32(ge * b2);
    }
    __syncthreads();

    int warp = tid >> 5, lane = tid & 31;
    int g = lane >> 2, q4 = lane & 3;
    int m0 = (warp & 3) * 16, n0 = (warp >> 2) * 32;

    float d[4][4];
    #pragma unroll
    for (int nt = 0; nt < 4; nt++)
        #pragma unroll
        for (int e = 0; e < 4; e++) d[nt][e] = 0.f;

    #pragma unroll 4
    for (int ks = 0; ks < 24; ks++) {
        int k0 = ks * 8;
        u32 a0 = s_t_u[(k0 + q4) * STRK + m0 + g];
        u32 a1 = s_t_u[(k0 + q4) * STRK + m0 + g + 8];
        u32 a2 = s_t_u[(k0 + q4 + 4) * STRK + m0 + g];
        u32 a3 = s_t_u[(k0 + q4 + 4) * STRK + m0 + g + 8];
        #pragma unroll
        for (int nt = 0; nt < 4; nt++) {
            int n = n0 + nt * 8;
            u32 b0 = s_w_u[(k0 + q4) * STRK + n + g];
            u32 b1 = s_w_u[(k0 + q4 + 4) * STRK + n + g];
            mma_tf32(d[nt], a0, a1, a2, a3, b0, b1);
        }
    }

    #pragma unroll
    for (int nt = 0; nt < 4; nt++) {
        int oc = n0 + nt * 8 + q4 * 2;
        int px = m0 + g;
        size_t a00 = ((size_t)(b * DIM + oc)) * HWn + (size_t)ch * 64;
        size_t a01 = a00 + HWn;
        dout[a00 + px]     = g_x1[a00 + px]     + d[nt][0];
        dout[a01 + px]     = g_x1[a01 + px]     + d[nt][1];
        dout[a00 + px + 8] = g_x1[a00 + px + 8] + d[nt][2];
        dout[a01 + px + 8] = g_x1[a01 + px + 8] + d[nt][3];
    }
}

extern "C" void kernel_launch(void* const* d_in, const int* in_sizes, int n_in,
                              void* d_out, int out_size)
{
    const float* x     = (const float*)d_in[0];
    const float* n1w   = (const float*)d_in[1];
    const float* n1b   = (const float*)d_in[2];
    const float* apin  = (const float*)d_in[3];
    const float* adw   = (const float*)d_in[4];
    const float* apout = (const float*)d_in[5];
    const float* n2w   = (const float*)d_in[6];
    const float* n2b   = (const float*)d_in[7];
    const float* fpin  = (const float*)d_in[8];
    const float* fdw   = (const float*)d_in[9];
    const float* ffft  = (const float*)d_in[10];
    const float* fpout = (const float*)d_in[11];
    float* out         = (float*)d_out;

    (void)in_sizes; (void)n_in; (void)out_size;

    cudaFuncSetAttribute(k_ln_pconv, cudaFuncAttributeMaxDynamicSharedMemorySize, 122880);
    cudaFuncSetAttribute(k_attn,     cudaFuncAttributeMaxDynamicSharedMemorySize, 102400);
    cudaFuncSetAttribute(k_ffn_out,  cudaFuncAttributeMaxDynamicSharedMemorySize, 110592);

    k_prep<<<CH6, 64>>>(ffft);

    k_ln_pconv<<<2048, 512, 122880>>>(x, n1w, n1b, apin, 0);
    k_dw<<<dim3(8, 2 * CH6), 256>>>(adw);
    k_attn<<<2048, 256, 102400>>>(x, apout);

    k_ln_pconv<<<2048, 512, 122880>>>(x, n2w, n2b, fpin, 1);
    k_dw<<<dim3(8, 2 * CH6), 256>>>(fdw);
    k_ffn_out<<<2048, 256, 110592>>>(fpout, out);
}

// round 6
// speedup vs baseline: 2.4611x; 1.5772x over previous
#include <cuda_runtime.h>
#include <math.h>

#define HWn   65536
#define Wimg  256
#define Himg  256
#define DIM   64
#define CH6   384
#define CH2   128
#define HID   192
#define EPS   1e-5f
#define STRK  72      // padded k-major stride for mma A-operand staging

typedef unsigned int u32;

// ---------------------------------------------------------------------------
// Scratch (device globals; no runtime allocation)
// ---------------------------------------------------------------------------
__device__ float g_h [(size_t)2 * CH6 * HWn];
__device__ float g_h2[(size_t)2 * CH6 * HWn];
__device__ float g_x1[(size_t)2 * DIM * HWn];
__device__ float g_gker[CH6 * 64];
__device__ int   g_isdelta[CH6];
__device__ int   g_alldelta;

// fragment-packed tf32 weights
__device__ uint4 g_pkA0[24 * 8 * 32];   // attn pin  [384x64] A-frags
__device__ uint4 g_pkA1[24 * 8 * 32];   // ffn  pin  [384x64] A-frags
__device__ uint2 g_pkB2[16 * 8 * 32];   // attn pout [64x128] B-frags
__device__ uint2 g_pkB3[24 * 8 * 32];   // ffn  pout [64x192] B-frags

__device__ __forceinline__ u32 to_tf32(float f) {
    u32 r; asm("cvt.rna.tf32.f32 %0, %1;" : "=r"(r) : "f"(f)); return r;
}
__device__ __forceinline__ void mma_tf32(float d[4], u32 a0, u32 a1, u32 a2, u32 a3,
                                         u32 b0, u32 b1) {
    asm volatile(
        "mma.sync.aligned.m16n8k8.row.col.f32.tf32.tf32.f32 "
        "{%0,%1,%2,%3}, {%4,%5,%6,%7}, {%8,%9}, {%0,%1,%2,%3};"
        : "+f"(d[0]), "+f"(d[1]), "+f"(d[2]), "+f"(d[3])
        : "r"(a0), "r"(a1), "r"(a2), "r"(a3), "r"(b0), "r"(b1));
}

// ---------------------------------------------------------------------------
// K0: FFN spectral kernel g_c = irfft2(fft_params_c) + delta flags
// ---------------------------------------------------------------------------
__global__ void k_prep(const float* __restrict__ fp) {
    int c = blockIdx.x;
    int t = threadIdx.x;
    int x = t >> 3, y = t & 7;
    float s = 0.f;
    #pragma unroll
    for (int kx = 0; kx < 8; kx++) {
        #pragma unroll
        for (int ky = 0; ky < 8; ky++) {
            float Sv = (ky <= 4) ? fp[c * 40 + kx * 5 + ky]
                                 : fp[c * 40 + (((8 - kx) & 7) * 5) + (8 - ky)];
            int m = (kx * x + ky * y) & 7;
            s += Sv * cospif((float)m * 0.25f);
        }
    }
    s *= (1.f / 64.f);
    g_gker[c * 64 + t] = s;
    float target = (t == 0) ? 1.f : 0.f;
    int ok = __syncthreads_and(fabsf(s - target) <= 1e-5f);
    if (t == 0) g_isdelta[c] = ok;
}

__global__ void k_alldelta() {
    int v = (threadIdx.x < CH6) ? g_isdelta[threadIdx.x] : 1;
    int all = __syncthreads_and(v);
    if (threadIdx.x == 0) g_alldelta = all;
}

// ---------------------------------------------------------------------------
// weight packers (tf32 fragment order)
// ---------------------------------------------------------------------------
__global__ void k_packA(const float* __restrict__ W, int which) {
    int s = blockIdx.x, ks = blockIdx.y, lane = threadIdx.x;
    int g = lane >> 2, q4 = lane & 3;
    int m0 = s * 16, k0 = ks * 8;
    uint4 v;
    v.x = to_tf32(W[(m0 + g) * 64 + k0 + q4]);
    v.y = to_tf32(W[(m0 + g + 8) * 64 + k0 + q4]);
    v.z = to_tf32(W[(m0 + g) * 64 + k0 + q4 + 4]);
    v.w = to_tf32(W[(m0 + g + 8) * 64 + k0 + q4 + 4]);
    (which ? g_pkA1 : g_pkA0)[(s * 8 + ks) * 32 + lane] = v;
}

__global__ void k_packB(const float* __restrict__ W, int which, int IC) {
    int ks = blockIdx.x, nt = blockIdx.y, lane = threadIdx.x;
    int g = lane >> 2, q4 = lane & 3;
    int n = nt * 8, k0 = ks * 8;
    uint2 v;
    v.x = to_tf32(W[(n + g) * IC + k0 + q4]);
    v.y = to_tf32(W[(n + g) * IC + k0 + q4 + 4]);
    (which ? g_pkB3 : g_pkB2)[(ks * 8 + nt) * 32 + lane] = v;
}

// ---------------------------------------------------------------------------
// K1/K4: fused LayerNorm + 1x1 conv [384oc x 64ic] via tf32 mma
// grid 2048 (b*1024+chunk), 256 threads; smem: s_in [64][72] only (18.4KB)
// warp w handles m-slabs {w, w+8, w+16}; A-frags from packed global
// ---------------------------------------------------------------------------
__global__ void __launch_bounds__(256)
k_ln_pconv(const float* __restrict__ xin,
           const float* __restrict__ nw,
           const float* __restrict__ nb,
           int which)       // 0: attn (in=xin, pkA0)  1: ffn (in=g_x1, pkA1)
{
    __shared__ u32 s_in[64 * STRK];

    const float* in = which ? g_x1 : xin;
    const uint4* pk = which ? g_pkA1 : g_pkA0;

    int tid = threadIdx.x;
    int b   = blockIdx.x >> 10;
    int ch  = blockIdx.x & 1023;
    size_t pxoff = (size_t)ch * 64;

    int warp = tid >> 5, lane = tid & 31;

    // LayerNorm: 8 warps x 8 rows
    #pragma unroll
    for (int r = 0; r < 8; r++) {
        int ic = warp * 8 + r;
        const float* xr = in + ((size_t)(b * DIM + ic)) * HWn + pxoff;
        float v0 = xr[lane * 2], v1 = xr[lane * 2 + 1];
        float s = v0 + v1;
        float q = v0 * v0 + v1 * v1;
        #pragma unroll
        for (int o = 16; o; o >>= 1) {
            s += __shfl_xor_sync(0xffffffffu, s, o);
            q += __shfl_xor_sync(0xffffffffu, q, o);
        }
        float mu  = s * (1.f / 64.f);
        float var = q * (1.f / 64.f) - mu * mu;
        float inv = rsqrtf(var + EPS);
        int j = lane * 2;
        float y0 = (v0 - mu) * inv * nw[j]     + nb[j];
        float y1 = (v1 - mu) * inv * nw[j + 1] + nb[j + 1];
        uint2 pkv = make_uint2(to_tf32(y0), to_tf32(y1));
        *(uint2*)&s_in[ic * STRK + j] = pkv;
    }
    __syncthreads();

    int g  = lane >> 2;
    int q4 = lane & 3;

    for (int s = warp; s < 24; s += 8) {
        int m0 = s * 16;
        float d[8][4];
        #pragma unroll
        for (int nt = 0; nt < 8; nt++)
            #pragma unroll
            for (int e = 0; e < 4; e++) d[nt][e] = 0.f;

        #pragma unroll
        for (int ks = 0; ks < 8; ks++) {
            uint4 af = pk[(s * 8 + ks) * 32 + lane];
            int k0 = ks * 8;
            #pragma unroll
            for (int nt = 0; nt < 8; nt++) {
                int n = nt * 8;
                u32 b0 = s_in[(k0 + q4) * STRK + n + g];
                u32 b1 = s_in[(k0 + q4 + 4) * STRK + n + g];
                mma_tf32(d[nt], af.x, af.y, af.z, af.w, b0, b1);
            }
        }
        #pragma unroll
        for (int nt = 0; nt < 8; nt++) {
            int px = nt * 8 + q4 * 2;
            *(float2*)&g_h[((size_t)(b * CH6 + m0 + g)) * HWn + pxoff + px] =
                make_float2(d[nt][0], d[nt][1]);
            *(float2*)&g_h[((size_t)(b * CH6 + m0 + g + 8)) * HWn + pxoff + px] =
                make_float2(d[nt][2], d[nt][3]);
        }
    }
}

// ---------------------------------------------------------------------------
// K4b: generic FFN spectral conv, in-place on g_h; near-noop when all-delta
// grid 2048 (b*1024+chunk), 256 threads
// ---------------------------------------------------------------------------
__global__ void __launch_bounds__(256)
k_spectral()
{
    if (g_alldelta) return;
    int b  = blockIdx.x >> 10;
    int ch = blockIdx.x & 1023;
    for (int c = threadIdx.x; c < CH6; c += 256) {
        if (g_isdelta[c]) continue;
        float* p = g_h + ((size_t)(b * CH6 + c)) * HWn + (size_t)ch * 64;
        float t[64];
        #pragma unroll
        for (int i = 0; i < 64; i++) t[i] = p[i];
        const float* gk = &g_gker[c * 64];
        float o[64];
        for (int i = 0; i < 8; i++)
            for (int j = 0; j < 8; j++) {
                float v = 0.f;
                for (int a = 0; a < 8; a++) {
                    int ri = ((i - a) & 7) * 8;
                    #pragma unroll
                    for (int bb = 0; bb < 8; bb++)
                        v += t[ri + ((j - bb) & 7)] * gk[a * 8 + bb];
                }
                o[i * 8 + j] = v;
            }
        #pragma unroll
        for (int i = 0; i < 64; i++) p[i] = o[i];
    }
}

// ---------------------------------------------------------------------------
// K2/K5: depthwise 3x3, rolling-row accumulation (3 LDS per output)
// grid (8 row-blocks, 768 planes), 256 threads (one col each), 32 rows/block
// ---------------------------------------------------------------------------
__global__ void __launch_bounds__(256)
k_dw(const float* __restrict__ wt)
{
    __shared__ float s[34][Wimg];
    int plane = blockIdx.y;
    int c = plane % CH6;
    int r0 = blockIdx.x * 32;
    int col = threadIdx.x;
    const float* ip = g_h  + (size_t)plane * HWn;
    float*       op = g_h2 + (size_t)plane * HWn;

    #pragma unroll
    for (int r = 0; r < 34; r++) {
        int gr = r0 + r - 1;
        s[r][col] = (gr >= 0 && gr < Himg) ? ip[gr * Wimg + col] : 0.f;
    }
    float w[9];
    #pragma unroll
    for (int i = 0; i < 9; i++) w[i] = __ldg(&wt[c * 9 + i]);
    __syncthreads();

    float p0 = 0.f, p1 = 0.f;
    #pragma unroll
    for (int r = 0; r < 34; r++) {
        float l   = (col > 0)        ? s[r][col - 1] : 0.f;
        float ctr = s[r][col];
        float rt  = (col < Wimg - 1) ? s[r][col + 1] : 0.f;
        float h0 = fmaf(l, w[0], fmaf(ctr, w[1], rt * w[2]));
        float h1 = fmaf(l, w[3], fmaf(ctr, w[4], rt * w[5]));
        float h2 = fmaf(l, w[6], fmaf(ctr, w[7], rt * w[8]));
        if (r >= 2) op[(r0 + r - 2) * Wimg + col] = p1 + h2;
        p1 = p0 + h1;
        p0 = h0;
    }
}

// ---------------------------------------------------------------------------
// K3: attention tail: t = v * circconv8x8(q,k); x1 = x + W2 @ t
// grid 2048, 256 threads; dynamic smem 64KB (q 32KB | k 32KB; t overlays)
// q/k rows XOR-swizzled by channel -> conflict-free conv reads
// ---------------------------------------------------------------------------
__global__ void __launch_bounds__(256)
k_attn(const float* __restrict__ x)
{
    extern __shared__ float sh[];
    float* s_q = sh;                    // [128][64], rows swizzled
    float* s_k = sh + 8192;             // [128][64], rows swizzled
    u32*   s_t_u = (u32*)sh;            // [128][STRK] tf32, overlays q (+k head)

    int tid = threadIdx.x;
    int b   = blockIdx.x >> 10;
    int ch  = blockIdx.x & 1023;
    size_t base = (size_t)b * CH6 * HWn + (size_t)ch * 64;

    for (int i = tid; i < CH2 * 64; i += 256) {
        int c = i >> 6, p = i & 63;
        int r = p >> 3, j = p & 7;
        int off = c * 64 + (((r ^ (c & 7)) << 3) | j);
        s_q[off] = g_h2[base + (size_t)c * HWn + p];
        s_k[off] = g_h2[base + (size_t)(CH2 + c) * HWn + p];
    }
    __syncthreads();

    // circular conv: thread = (channel, half); rows i0..i0+3
    int c  = tid >> 1;
    int i0 = (tid & 1) * 4;
    int sw = (c & 7);
    float o[4][8];
    #pragma unroll
    for (int di = 0; di < 4; di++)
        #pragma unroll
        for (int j = 0; j < 8; j++) o[di][j] = 0.f;
    {
        const float* qb = &s_q[c * 64];
        const float* kb = &s_k[c * 64];
        #pragma unroll 2
        for (int a = 0; a < 8; a++) {
            int kph = (a ^ sw) << 3;
            float kv[8];
            *(float4*)&kv[0] = *(const float4*)&kb[kph];
            *(float4*)&kv[4] = *(const float4*)&kb[kph + 4];
            #pragma unroll
            for (int di = 0; di < 4; di++) {
                int rr = (i0 + di - a) & 7;
                int ph = (rr ^ sw) << 3;
                float qv[8];
                *(float4*)&qv[0] = *(const float4*)&qb[ph];
                *(float4*)&qv[4] = *(const float4*)&qb[ph + 4];
                #pragma unroll
                for (int bb = 0; bb < 8; bb++) {
                    float kvv = kv[bb];
                    #pragma unroll
                    for (int j = 0; j < 8; j++)
                        o[di][j] += qv[(j - bb) & 7] * kvv;
                }
            }
        }
    }
    {
        const float* vbase = g_h2 + base + (size_t)(2 * CH2 + c) * HWn;
        #pragma unroll
        for (int di = 0; di < 4; di++) {
            float4 v0 = *(const float4*)&vbase[(i0 + di) * 8];
            float4 v1 = *(const float4*)&vbase[(i0 + di) * 8 + 4];
            o[di][0] *= v0.x; o[di][1] *= v0.y; o[di][2] *= v0.z; o[di][3] *= v0.w;
            o[di][4] *= v1.x; o[di][5] *= v1.y; o[di][6] *= v1.z; o[di][7] *= v1.w;
        }
    }
    __syncthreads();     // all conv reads of q/k done; safe to overlay t
    #pragma unroll
    for (int di = 0; di < 4; di++) {
        uint4 p0 = make_uint4(to_tf32(o[di][0]), to_tf32(o[di][1]),
                              to_tf32(o[di][2]), to_tf32(o[di][3]));
        uint4 p1 = make_uint4(to_tf32(o[di][4]), to_tf32(o[di][5]),
                              to_tf32(o[di][6]), to_tf32(o[di][7]));
        *(uint4*)&s_t_u[c * STRK + (i0 + di) * 8]     = p0;
        *(uint4*)&s_t_u[c * STRK + (i0 + di) * 8 + 4] = p1;
    }
    __syncthreads();

    // mma: M=64px, N=64oc, K=128; warp: m0=(w&3)*16, n0=(w>>2)*32
    int warp = tid >> 5, lane = tid & 31;
    int g = lane >> 2, q4 = lane & 3;
    int m0 = (warp & 3) * 16, n0 = (warp >> 2) * 32;
    int ntg0 = (warp >> 2) * 4;

    float d[4][4];
    #pragma unroll
    for (int nt = 0; nt < 4; nt++)
        #pragma unroll
        for (int e = 0; e < 4; e++) d[nt][e] = 0.f;

    #pragma unroll 4
    for (int ks = 0; ks < 16; ks++) {
        int k0 = ks * 8;
        u32 a0 = s_t_u[(k0 + q4) * STRK + m0 + g];
        u32 a1 = s_t_u[(k0 + q4) * STRK + m0 + g + 8];
        u32 a2 = s_t_u[(k0 + q4 + 4) * STRK + m0 + g];
        u32 a3 = s_t_u[(k0 + q4 + 4) * STRK + m0 + g + 8];
        #pragma unroll
        for (int nt = 0; nt < 4; nt++) {
            uint2 bf = g_pkB2[(ks * 8 + ntg0 + nt) * 32 + lane];
            mma_tf32(d[nt], a0, a1, a2, a3, bf.x, bf.y);
        }
    }

    #pragma unroll
    for (int nt = 0; nt < 4; nt++) {
        int oc = n0 + nt * 8 + q4 * 2;
        int px = m0 + g;
        size_t a00 = ((size_t)(b * DIM + oc)) * HWn + (size_t)ch * 64;
        size_t a01 = a00 + HWn;
        g_x1[a00 + px]     = x[a00 + px]     + d[nt][0];
        g_x1[a01 + px]     = x[a01 + px]     + d[nt][1];
        g_x1[a00 + px + 8] = x[a00 + px + 8] + d[nt][2];
        g_x1[a01 + px + 8] = x[a01 + px + 8] + d[nt][3];
    }
}

// ---------------------------------------------------------------------------
// K6: FFN tail: t = gelu(h2a)*h2b; out = x1 + W3 @ t
// grid 2048, 256 threads; dynamic smem 55.3KB (s_t only; W3 packed-global)
// ---------------------------------------------------------------------------
__global__ void __launch_bounds__(256)
k_ffn_out(float* __restrict__ dout)
{
    extern __shared__ float sh[];
    u32* s_t_u = (u32*)sh;              // [192][STRK]

    int tid = threadIdx.x;
    int b   = blockIdx.x >> 10;
    int ch  = blockIdx.x & 1023;
    size_t base = (size_t)b * CH6 * HWn + (size_t)ch * 64;

    for (int i = tid; i < HID * 64; i += 256) {
        int c = i >> 6, p = i & 63;
        float a  = g_h2[base + (size_t)c * HWn + p];
        float b2 = g_h2[base + (size_t)(HID + c) * HWn + p];
        float ge = 0.5f * a * (1.f + erff(a * 0.70710678118654752f));
        s_t_u[c * STRK + p] = to_tf32(ge * b2);
    }
    __syncthreads();

    int warp = tid >> 5, lane = tid & 31;
    int g = lane >> 2, q4 = lane & 3;
    int m0 = (warp & 3) * 16, n0 = (warp >> 2) * 32;
    int ntg0 = (warp >> 2) * 4;

    float d[4][4];
    #pragma unroll
    for (int nt = 0; nt < 4; nt++)
        #pragma unroll
        for (int e = 0; e < 4; e++) d[nt][e] = 0.f;

    #pragma unroll 4
    for (int ks = 0; ks < 24; ks++) {
        int k0 = ks * 8;
        u32 a0 = s_t_u[(k0 + q4) * STRK + m0 + g];
        u32 a1 = s_t_u[(k0 + q4) * STRK + m0 + g + 8];
        u32 a2 = s_t_u[(k0 + q4 + 4) * STRK + m0 + g];
        u32 a3 = s_t_u[(k0 + q4 + 4) * STRK + m0 + g + 8];
        #pragma unroll
        for (int nt = 0; nt < 4; nt++) {
            uint2 bf = g_pkB3[(ks * 8 + ntg0 + nt) * 32 + lane];
            mma_tf32(d[nt], a0, a1, a2, a3, bf.x, bf.y);
        }
    }

    #pragma unroll
    for (int nt = 0; nt < 4; nt++) {
        int oc = n0 + nt * 8 + q4 * 2;
        int px = m0 + g;
        size_t a00 = ((size_t)(b * DIM + oc)) * HWn + (size_t)ch * 64;
        size_t a01 = a00 + HWn;
        dout[a00 + px]     = g_x1[a00 + px]     + d[nt][0];
        dout[a01 + px]     = g_x1[a01 + px]     + d[nt][1];
        dout[a00 + px + 8] = g_x1[a00 + px + 8] + d[nt][2];
        dout[a01 + px + 8] = g_x1[a01 + px + 8] + d[nt][3];
    }
}

// ---------------------------------------------------------------------------
// launcher
// ---------------------------------------------------------------------------
extern "C" void kernel_launch(void* const* d_in, const int* in_sizes, int n_in,
                              void* d_out, int out_size)
{
    const float* x     = (const float*)d_in[0];
    const float* n1w   = (const float*)d_in[1];
    const float* n1b   = (const float*)d_in[2];
    const float* apin  = (const float*)d_in[3];
    const float* adw   = (const float*)d_in[4];
    const float* apout = (const float*)d_in[5];
    const float* n2w   = (const float*)d_in[6];
    const float* n2b   = (const float*)d_in[7];
    const float* fpin  = (const float*)d_in[8];
    const float* fdw   = (const float*)d_in[9];
    const float* ffft  = (const float*)d_in[10];
    const float* fpout = (const float*)d_in[11];
    float* out         = (float*)d_out;

    (void)in_sizes; (void)n_in; (void)out_size;

    cudaFuncSetAttribute(k_attn,    cudaFuncAttributeMaxDynamicSharedMemorySize, 65536);
    cudaFuncSetAttribute(k_ffn_out, cudaFuncAttributeMaxDynamicSharedMemorySize, 55296);

    // preparation (tiny)
    k_prep<<<CH6, 64>>>(ffft);
    k_alldelta<<<1, 384>>>();
    k_packA<<<dim3(24, 8), 32>>>(apin, 0);
    k_packA<<<dim3(24, 8), 32>>>(fpin, 1);
    k_packB<<<dim3(16, 8), 32>>>(apout, 0, CH2);
    k_packB<<<dim3(24, 8), 32>>>(fpout, 1, HID);

    // attention branch
    k_ln_pconv<<<2048, 256>>>(x, n1w, n1b, 0);
    k_dw<<<dim3(8, 2 * CH6), 256>>>(adw);
    k_attn<<<2048, 256, 65536>>>(x);

    // FFN branch
    k_ln_pconv<<<2048, 256>>>(x, n2w, n2b, 1);
    k_spectral<<<2048, 256>>>();
    k_dw<<<dim3(8, 2 * CH6), 256>>>(fdw);
    k_ffn_out<<<2048, 256, 55296>>>(out);
}

// round 7
// speedup vs baseline: 2.7079x; 1.1003x over previous
#include <cuda_runtime.h>
#include <cuda_bf16.h>
#include <math.h>

#define HWn   65536
#define Wimg  256
#define Himg  256
#define DIM   64
#define CH6   384
#define CH2   128
#define HID   192
#define EPS   1e-5f
#define STRK  72      // padded k-major stride for mma A-operand staging

typedef unsigned int u32;
typedef __nv_bfloat16  bf16;
typedef __nv_bfloat162 bf162;

// ---------------------------------------------------------------------------
// Scratch (device globals; no runtime allocation)
// ---------------------------------------------------------------------------
__device__ bf16  g_h [(size_t)2 * CH6 * HWn];   // pconv output (bf16 storage)
__device__ bf16  g_h2[(size_t)2 * CH6 * HWn];   // dwconv output (bf16 storage)
__device__ float g_x1[(size_t)2 * DIM * HWn];   // residual carrier (fp32)
__device__ float g_gker[CH6 * 64];
__device__ int   g_isdelta[CH6];
__device__ int   g_alldelta;

// fragment-packed tf32 weights
__device__ uint4 g_pkA0[24 * 8 * 32];   // attn pin  [384x64] A-frags
__device__ uint4 g_pkA1[24 * 8 * 32];   // ffn  pin  [384x64] A-frags
__device__ uint2 g_pkB2[16 * 8 * 32];   // attn pout [64x128] B-frags
__device__ uint2 g_pkB3[24 * 8 * 32];   // ffn  pout [64x192] B-frags

__device__ __forceinline__ u32 to_tf32(float f) {
    u32 r; asm("cvt.rna.tf32.f32 %0, %1;" : "=r"(r) : "f"(f)); return r;
}
__device__ __forceinline__ void mma_tf32(float d[4], u32 a0, u32 a1, u32 a2, u32 a3,
                                         u32 b0, u32 b1) {
    asm volatile(
        "mma.sync.aligned.m16n8k8.row.col.f32.tf32.tf32.f32 "
        "{%0,%1,%2,%3}, {%4,%5,%6,%7}, {%8,%9}, {%0,%1,%2,%3};"
        : "+f"(d[0]), "+f"(d[1]), "+f"(d[2]), "+f"(d[3])
        : "r"(a0), "r"(a1), "r"(a2), "r"(a3), "r"(b0), "r"(b1));
}

// ---------------------------------------------------------------------------
// K0: FFN spectral kernel g_c = irfft2(fft_params_c) + delta flags
// ---------------------------------------------------------------------------
__global__ void k_prep(const float* __restrict__ fp) {
    int c = blockIdx.x;
    int t = threadIdx.x;
    int x = t >> 3, y = t & 7;
    float s = 0.f;
    #pragma unroll
    for (int kx = 0; kx < 8; kx++) {
        #pragma unroll
        for (int ky = 0; ky < 8; ky++) {
            float Sv = (ky <= 4) ? fp[c * 40 + kx * 5 + ky]
                                 : fp[c * 40 + (((8 - kx) & 7) * 5) + (8 - ky)];
            int m = (kx * x + ky * y) & 7;
            s += Sv * cospif((float)m * 0.25f);
        }
    }
    s *= (1.f / 64.f);
    g_gker[c * 64 + t] = s;
    float target = (t == 0) ? 1.f : 0.f;
    int ok = __syncthreads_and(fabsf(s - target) <= 1e-5f);
    if (t == 0) g_isdelta[c] = ok;
}

__global__ void k_alldelta() {
    int v = (threadIdx.x < CH6) ? g_isdelta[threadIdx.x] : 1;
    int all = __syncthreads_and(v);
    if (threadIdx.x == 0) g_alldelta = all;
}

// ---------------------------------------------------------------------------
// weight packers (tf32 fragment order)
// ---------------------------------------------------------------------------
__global__ void k_packA(const float* __restrict__ W, int which) {
    int s = blockIdx.x, ks = blockIdx.y, lane = threadIdx.x;
    int g = lane >> 2, q4 = lane & 3;
    int m0 = s * 16, k0 = ks * 8;
    uint4 v;
    v.x = to_tf32(W[(m0 + g) * 64 + k0 + q4]);
    v.y = to_tf32(W[(m0 + g + 8) * 64 + k0 + q4]);
    v.z = to_tf32(W[(m0 + g) * 64 + k0 + q4 + 4]);
    v.w = to_tf32(W[(m0 + g + 8) * 64 + k0 + q4 + 4]);
    (which ? g_pkA1 : g_pkA0)[(s * 8 + ks) * 32 + lane] = v;
}

__global__ void k_packB(const float* __restrict__ W, int which, int IC) {
    int ks = blockIdx.x, nt = blockIdx.y, lane = threadIdx.x;
    int g = lane >> 2, q4 = lane & 3;
    int n = nt * 8, k0 = ks * 8;
    uint2 v;
    v.x = to_tf32(W[(n + g) * IC + k0 + q4]);
    v.y = to_tf32(W[(n + g) * IC + k0 + q4 + 4]);
    (which ? g_pkB3 : g_pkB2)[(ks * 8 + nt) * 32 + lane] = v;
}

// ---------------------------------------------------------------------------
// K1/K4: fused LayerNorm + 1x1 conv [384oc x 64ic] via tf32 mma -> bf16 out
// grid 2048 (b*1024+chunk), 256 threads; smem s_in [64][72] (18.4KB)
// ---------------------------------------------------------------------------
__global__ void __launch_bounds__(256)
k_ln_pconv(const float* __restrict__ xin,
           const float* __restrict__ nw,
           const float* __restrict__ nb,
           int which)       // 0: attn (in=xin, pkA0)  1: ffn (in=g_x1, pkA1)
{
    __shared__ u32 s_in[64 * STRK];

    const float* in = which ? g_x1 : xin;
    const uint4* pk = which ? g_pkA1 : g_pkA0;

    int tid = threadIdx.x;
    int b   = blockIdx.x >> 10;
    int ch  = blockIdx.x & 1023;
    size_t pxoff = (size_t)ch * 64;

    int warp = tid >> 5, lane = tid & 31;

    // LayerNorm: 8 warps x 8 rows
    #pragma unroll
    for (int r = 0; r < 8; r++) {
        int ic = warp * 8 + r;
        const float* xr = in + ((size_t)(b * DIM + ic)) * HWn + pxoff;
        float v0 = xr[lane * 2], v1 = xr[lane * 2 + 1];
        float s = v0 + v1;
        float q = v0 * v0 + v1 * v1;
        #pragma unroll
        for (int o = 16; o; o >>= 1) {
            s += __shfl_xor_sync(0xffffffffu, s, o);
            q += __shfl_xor_sync(0xffffffffu, q, o);
        }
        float mu  = s * (1.f / 64.f);
        float var = q * (1.f / 64.f) - mu * mu;
        float inv = rsqrtf(var + EPS);
        int j = lane * 2;
        float y0 = (v0 - mu) * inv * nw[j]     + nb[j];
        float y1 = (v1 - mu) * inv * nw[j + 1] + nb[j + 1];
        uint2 pkv = make_uint2(to_tf32(y0), to_tf32(y1));
        *(uint2*)&s_in[ic * STRK + j] = pkv;
    }
    __syncthreads();

    int g  = lane >> 2;
    int q4 = lane & 3;

    for (int s = warp; s < 24; s += 8) {
        int m0 = s * 16;
        float d[8][4];
        #pragma unroll
        for (int nt = 0; nt < 8; nt++)
            #pragma unroll
            for (int e = 0; e < 4; e++) d[nt][e] = 0.f;

        #pragma unroll
        for (int ks = 0; ks < 8; ks++) {
            uint4 af = pk[(s * 8 + ks) * 32 + lane];
            int k0 = ks * 8;
            #pragma unroll
            for (int nt = 0; nt < 8; nt++) {
                int n = nt * 8;
                u32 b0 = s_in[(k0 + q4) * STRK + n + g];
                u32 b1 = s_in[(k0 + q4 + 4) * STRK + n + g];
                mma_tf32(d[nt], af.x, af.y, af.z, af.w, b0, b1);
            }
        }
        #pragma unroll
        for (int nt = 0; nt < 8; nt++) {
            int px = nt * 8 + q4 * 2;
            *(bf162*)&g_h[((size_t)(b * CH6 + m0 + g)) * HWn + pxoff + px] =
                __floats2bfloat162_rn(d[nt][0], d[nt][1]);
            *(bf162*)&g_h[((size_t)(b * CH6 + m0 + g + 8)) * HWn + pxoff + px] =
                __floats2bfloat162_rn(d[nt][2], d[nt][3]);
        }
    }
}

// ---------------------------------------------------------------------------
// K4b: generic FFN spectral conv, in-place on g_h; near-noop when all-delta
// ---------------------------------------------------------------------------
__global__ void __launch_bounds__(256)
k_spectral()
{
    if (g_alldelta) return;
    int b  = blockIdx.x >> 10;
    int ch = blockIdx.x & 1023;
    for (int c = threadIdx.x; c < CH6; c += 256) {
        if (g_isdelta[c]) continue;
        bf16* p = g_h + ((size_t)(b * CH6 + c)) * HWn + (size_t)ch * 64;
        float t[64];
        #pragma unroll
        for (int i = 0; i < 64; i++) t[i] = __bfloat162float(p[i]);
        const float* gk = &g_gker[c * 64];
        float o[64];
        for (int i = 0; i < 8; i++)
            for (int j = 0; j < 8; j++) {
                float v = 0.f;
                for (int a = 0; a < 8; a++) {
                    int ri = ((i - a) & 7) * 8;
                    #pragma unroll
                    for (int bb = 0; bb < 8; bb++)
                        v += t[ri + ((j - bb) & 7)] * gk[a * 8 + bb];
                }
                o[i * 8 + j] = v;
            }
        #pragma unroll
        for (int i = 0; i < 64; i++) p[i] = __float2bfloat16(o[i]);
    }
}

// ---------------------------------------------------------------------------
// K2/K5: depthwise 3x3 (bf16 in/out), rolling-row accumulation
// grid (8 row-blocks, 768 planes), 256 threads, 32 rows/block
// ---------------------------------------------------------------------------
__global__ void __launch_bounds__(256)
k_dw(const float* __restrict__ wt)
{
    __shared__ float s[34][Wimg];
    int plane = blockIdx.y;
    int c = plane % CH6;
    int r0 = blockIdx.x * 32;
    int col = threadIdx.x;
    const bf16* ip = g_h  + (size_t)plane * HWn;
    bf16*       op = g_h2 + (size_t)plane * HWn;

    #pragma unroll
    for (int r = 0; r < 34; r++) {
        int gr = r0 + r - 1;
        s[r][col] = (gr >= 0 && gr < Himg) ? __bfloat162float(ip[gr * Wimg + col]) : 0.f;
    }
    float w[9];
    #pragma unroll
    for (int i = 0; i < 9; i++) w[i] = __ldg(&wt[c * 9 + i]);
    __syncthreads();

    float p0 = 0.f, p1 = 0.f;
    #pragma unroll
    for (int r = 0; r < 34; r++) {
        float l   = (col > 0)        ? s[r][col - 1] : 0.f;
        float ctr = s[r][col];
        float rt  = (col < Wimg - 1) ? s[r][col + 1] : 0.f;
        float h0 = fmaf(l, w[0], fmaf(ctr, w[1], rt * w[2]));
        float h1 = fmaf(l, w[3], fmaf(ctr, w[4], rt * w[5]));
        float h2 = fmaf(l, w[6], fmaf(ctr, w[7], rt * w[8]));
        if (r >= 2) op[(r0 + r - 2) * Wimg + col] = __float2bfloat16(p1 + h2);
        p1 = p0 + h1;
        p0 = h0;
    }
}

// ---------------------------------------------------------------------------
// K3: attention tail: t = v * circconv8x8(q,k); x1 = x + W2 @ t
// grid 2048, 256 threads; dynamic smem 64KB; q/k rows XOR-swizzled
// ---------------------------------------------------------------------------
__global__ void __launch_bounds__(256)
k_attn(const float* __restrict__ x)
{
    extern __shared__ float sh[];
    float* s_q = sh;                    // [128][64], rows swizzled
    float* s_k = sh + 8192;             // [128][64], rows swizzled
    u32*   s_t_u = (u32*)sh;            // [128][STRK] tf32, overlays q (+k head)

    int tid = threadIdx.x;
    int b   = blockIdx.x >> 10;
    int ch  = blockIdx.x & 1023;
    size_t base = (size_t)b * CH6 * HWn + (size_t)ch * 64;

    // stage q,k (bf162 loads -> fp32 swizzled smem)
    for (int i = tid; i < CH2 * 32; i += 256) {
        int c = i >> 5, p2 = (i & 31) * 2;
        int r = p2 >> 3, j = p2 & 7;
        int off = c * 64 + (((r ^ (c & 7)) << 3) | j);
        bf162 qv = *(const bf162*)&g_h2[base + (size_t)c * HWn + p2];
        bf162 kv = *(const bf162*)&g_h2[base + (size_t)(CH2 + c) * HWn + p2];
        *(float2*)&s_q[off] = __bfloat1622float2(qv);
        *(float2*)&s_k[off] = __bfloat1622float2(kv);
    }
    __syncthreads();

    // circular conv: thread = (channel, half); rows i0..i0+3
    int c  = tid >> 1;
    int i0 = (tid & 1) * 4;
    int sw = (c & 7);
    float o[4][8];
    #pragma unroll
    for (int di = 0; di < 4; di++)
        #pragma unroll
        for (int j = 0; j < 8; j++) o[di][j] = 0.f;
    {
        const float* qb = &s_q[c * 64];
        const float* kb = &s_k[c * 64];
        #pragma unroll 2
        for (int a = 0; a < 8; a++) {
            int kph = (a ^ sw) << 3;
            float kv[8];
            *(float4*)&kv[0] = *(const float4*)&kb[kph];
            *(float4*)&kv[4] = *(const float4*)&kb[kph + 4];
            #pragma unroll
            for (int di = 0; di < 4; di++) {
                int rr = (i0 + di - a) & 7;
                int ph = (rr ^ sw) << 3;
                float qv[8];
                *(float4*)&qv[0] = *(const float4*)&qb[ph];
                *(float4*)&qv[4] = *(const float4*)&qb[ph + 4];
                #pragma unroll
                for (int bb = 0; bb < 8; bb++) {
                    float kvv = kv[bb];
                    #pragma unroll
                    for (int j = 0; j < 8; j++)
                        o[di][j] += qv[(j - bb) & 7] * kvv;
                }
            }
        }
    }
    {
        const bf16* vbase = g_h2 + base + (size_t)(2 * CH2 + c) * HWn;
        #pragma unroll
        for (int di = 0; di < 4; di++) {
            #pragma unroll
            for (int hh = 0; hh < 4; hh++) {
                float2 vv = __bfloat1622float2(
                    *(const bf162*)&vbase[(i0 + di) * 8 + hh * 2]);
                o[di][hh * 2]     *= vv.x;
                o[di][hh * 2 + 1] *= vv.y;
            }
        }
    }
    __syncthreads();     // all conv reads of q/k done; safe to overlay t
    #pragma unroll
    for (int di = 0; di < 4; di++) {
        uint4 p0 = make_uint4(to_tf32(o[di][0]), to_tf32(o[di][1]),
                              to_tf32(o[di][2]), to_tf32(o[di][3]));
        uint4 p1 = make_uint4(to_tf32(o[di][4]), to_tf32(o[di][5]),
                              to_tf32(o[di][6]), to_tf32(o[di][7]));
        *(uint4*)&s_t_u[c * STRK + (i0 + di) * 8]     = p0;
        *(uint4*)&s_t_u[c * STRK + (i0 + di) * 8 + 4] = p1;
    }
    __syncthreads();

    // mma: M=64px, N=64oc, K=128
    int warp = tid >> 5, lane = tid & 31;
    int g = lane >> 2, q4 = lane & 3;
    int m0 = (warp & 3) * 16, n0 = (warp >> 2) * 32;
    int ntg0 = (warp >> 2) * 4;

    float d[4][4];
    #pragma unroll
    for (int nt = 0; nt < 4; nt++)
        #pragma unroll
        for (int e = 0; e < 4; e++) d[nt][e] = 0.f;

    #pragma unroll 4
    for (int ks = 0; ks < 16; ks++) {
        int k0 = ks * 8;
        u32 a0 = s_t_u[(k0 + q4) * STRK + m0 + g];
        u32 a1 = s_t_u[(k0 + q4) * STRK + m0 + g + 8];
        u32 a2 = s_t_u[(k0 + q4 + 4) * STRK + m0 + g];
        u32 a3 = s_t_u[(k0 + q4 + 4) * STRK + m0 + g + 8];
        #pragma unroll
        for (int nt = 0; nt < 4; nt++) {
            uint2 bf = g_pkB2[(ks * 8 + ntg0 + nt) * 32 + lane];
            mma_tf32(d[nt], a0, a1, a2, a3, bf.x, bf.y);
        }
    }

    #pragma unroll
    for (int nt = 0; nt < 4; nt++) {
        int oc = n0 + nt * 8 + q4 * 2;
        int px = m0 + g;
        size_t a00 = ((size_t)(b * DIM + oc)) * HWn + (size_t)ch * 64;
        size_t a01 = a00 + HWn;
        g_x1[a00 + px]     = x[a00 + px]     + d[nt][0];
        g_x1[a01 + px]     = x[a01 + px]     + d[nt][1];
        g_x1[a00 + px + 8] = x[a00 + px + 8] + d[nt][2];
        g_x1[a01 + px + 8] = x[a01 + px + 8] + d[nt][3];
    }
}

// ---------------------------------------------------------------------------
// K6: FFN tail: t = gelu(h2a)*h2b; out = x1 + W3 @ t
// grid 2048, 256 threads; dynamic smem 55.3KB
// ---------------------------------------------------------------------------
__global__ void __launch_bounds__(256)
k_ffn_out(float* __restrict__ dout)
{
    extern __shared__ float sh[];
    u32* s_t_u = (u32*)sh;              // [192][STRK]

    int tid = threadIdx.x;
    int b   = blockIdx.x >> 10;
    int ch  = blockIdx.x & 1023;
    size_t base = (size_t)b * CH6 * HWn + (size_t)ch * 64;

    for (int i = tid; i < HID * 32; i += 256) {
        int c = i >> 5, p2 = (i & 31) * 2;
        float2 av = __bfloat1622float2(
            *(const bf162*)&g_h2[base + (size_t)c * HWn + p2]);
        float2 bv = __bfloat1622float2(
            *(const bf162*)&g_h2[base + (size_t)(HID + c) * HWn + p2]);
        float g0 = 0.5f * av.x * (1.f + erff(av.x * 0.70710678118654752f));
        float g1 = 0.5f * av.y * (1.f + erff(av.y * 0.70710678118654752f));
        uint2 pk = make_uint2(to_tf32(g0 * bv.x), to_tf32(g1 * bv.y));
        *(uint2*)&s_t_u[c * STRK + p2] = pk;
    }
    __syncthreads();

    int warp = tid >> 5, lane = tid & 31;
    int g = lane >> 2, q4 = lane & 3;
    int m0 = (warp & 3) * 16, n0 = (warp >> 2) * 32;
    int ntg0 = (warp >> 2) * 4;

    float d[4][4];
    #pragma unroll
    for (int nt = 0; nt < 4; nt++)
        #pragma unroll
        for (int e = 0; e < 4; e++) d[nt][e] = 0.f;

    #pragma unroll 4
    for (int ks = 0; ks < 24; ks++) {
        int k0 = ks * 8;
        u32 a0 = s_t_u[(k0 + q4) * STRK + m0 + g];
        u32 a1 = s_t_u[(k0 + q4) * STRK + m0 + g + 8];
        u32 a2 = s_t_u[(k0 + q4 + 4) * STRK + m0 + g];
        u32 a3 = s_t_u[(k0 + q4 + 4) * STRK + m0 + g + 8];
        #pragma unroll
        for (int nt = 0; nt < 4; nt++) {
            uint2 bf = g_pkB3[(ks * 8 + ntg0 + nt) * 32 + lane];
            mma_tf32(d[nt], a0, a1, a2, a3, bf.x, bf.y);
        }
    }

    #pragma unroll
    for (int nt = 0; nt < 4; nt++) {
        int oc = n0 + nt * 8 + q4 * 2;
        int px = m0 + g;
        size_t a00 = ((size_t)(b * DIM + oc)) * HWn + (size_t)ch * 64;
        size_t a01 = a00 + HWn;
        dout[a00 + px]     = g_x1[a00 + px]     + d[nt][0];
        dout[a01 + px]     = g_x1[a01 + px]     + d[nt][1];
        dout[a00 + px + 8] = g_x1[a00 + px + 8] + d[nt][2];
        dout[a01 + px + 8] = g_x1[a01 + px + 8] + d[nt][3];
    }
}

// ---------------------------------------------------------------------------
// launcher
// ---------------------------------------------------------------------------
extern "C" void kernel_launch(void* const* d_in, const int* in_sizes, int n_in,
                              void* d_out, int out_size)
{
    const float* x     = (const float*)d_in[0];
    const float* n1w   = (const float*)d_in[1];
    const float* n1b   = (const float*)d_in[2];
    const float* apin  = (const float*)d_in[3];
    const float* adw   = (const float*)d_in[4];
    const float* apout = (const float*)d_in[5];
    const float* n2w   = (const float*)d_in[6];
    const float* n2b   = (const float*)d_in[7];
    const float* fpin  = (const float*)d_in[8];
    const float* fdw   = (const float*)d_in[9];
    const float* ffft  = (const float*)d_in[10];
    const float* fpout = (const float*)d_in[11];
    float* out         = (float*)d_out;

    (void)in_sizes; (void)n_in; (void)out_size;

    cudaFuncSetAttribute(k_attn,    cudaFuncAttributeMaxDynamicSharedMemorySize, 65536);
    cudaFuncSetAttribute(k_ffn_out, cudaFuncAttributeMaxDynamicSharedMemorySize, 55296);

    // preparation (tiny)
    k_prep<<<CH6, 64>>>(ffft);
    k_alldelta<<<1, 384>>>();
    k_packA<<<dim3(24, 8), 32>>>(apin, 0);
    k_packA<<<dim3(24, 8), 32>>>(fpin, 1);
    k_packB<<<dim3(16, 8), 32>>>(apout, 0, CH2);
    k_packB<<<dim3(24, 8), 32>>>(fpout, 1, HID);

    // attention branch
    k_ln_pconv<<<2048, 256>>>(x, n1w, n1b, 0);
    k_dw<<<dim3(8, 2 * CH6), 256>>>(adw);
    k_attn<<<2048, 256, 65536>>>(x);

    // FFN branch
    k_ln_pconv<<<2048, 256>>>(x, n2w, n2b, 1);
    k_spectral<<<2048, 256>>>();
    k_dw<<<dim3(8, 2 * CH6), 256>>>(fdw);
    k_ffn_out<<<2048, 256, 55296>>>(out);
}